// round 2
// baseline (speedup 1.0000x reference)
#include <cuda_runtime.h>
#include <cstddef>

#define SPI 9          // spiral length
#define BM  128        // rows per block in the GEMM kernels
#define TM  8          // rows per thread

// ---------------------------------------------------------------------------
// Scratch (ping-pong). Sized for B=8, N=50000.
//   bufA: holds layer0 out (16ch) then layer2 out (64ch)  -> 8*50000*64 floats
//   bufB: holds layer1 out (32ch)                          -> 8*50000*32 floats
// ---------------------------------------------------------------------------
__device__ float g_bufA[(size_t)8 * 50000 * 64];
__device__ float g_bufB[(size_t)8 * 50000 * 32];

// Packed fp32x2 FMA: d = a*b + d (lane-wise). This is the 2x fp32 path on
// Blackwell (FFMA2); plain FFMA-3reg runs at half rate.
__device__ __forceinline__ void ffma2(float2 &d, const float2 &a, const float2 &b) {
    unsigned long long       &du = reinterpret_cast<unsigned long long &>(d);
    const unsigned long long &au = reinterpret_cast<const unsigned long long &>(a);
    const unsigned long long &bu = reinterpret_cast<const unsigned long long &>(b);
    asm("fma.rn.f32x2 %0, %1, %2, %0;" : "+l"(du) : "l"(au), "l"(bu));
}

// ---------------------------------------------------------------------------
// Layer 0: Cin=3 -> Cout=16.  Thread-per-vertex; W0 (27x16) in smem.
// ---------------------------------------------------------------------------
__global__ void layer0_kernel(const float *__restrict__ X,   // [B,N,3]
                              const int   *__restrict__ idx, // [N,S]
                              const float *__restrict__ W,   // [27,16]
                              const float *__restrict__ bias,// [16]
                              float *__restrict__ Y,         // [B,N,16]
                              int N) {
    __shared__ float Ws[27 * 16];
    __shared__ float bs[16];
    int tid = threadIdx.x;
    for (int t = tid; t < 27 * 16; t += blockDim.x) Ws[t] = W[t];   // FIXED: strided fill
    if (tid < 16) bs[tid] = bias[tid];
    __syncthreads();

    int n = blockIdx.x * blockDim.x + tid;
    int b = blockIdx.y;
    if (n >= N) return;

    float2 acc[8];
#pragma unroll
    for (int j = 0; j < 8; j++) acc[j] = make_float2(bs[2 * j], bs[2 * j + 1]);

    const float *Xb = X + (size_t)b * N * 3;
#pragma unroll
    for (int s = 0; s < SPI; s++) {
        int r = idx[n * SPI + s];
        float xv[3];
        xv[0] = __ldg(Xb + (size_t)r * 3 + 0);
        xv[1] = __ldg(Xb + (size_t)r * 3 + 1);
        xv[2] = __ldg(Xb + (size_t)r * 3 + 2);
#pragma unroll
        for (int c = 0; c < 3; c++) {
            const float *wrow = Ws + (s * 3 + c) * 16;
            float2 vv = make_float2(xv[c], xv[c]);
#pragma unroll
            for (int j = 0; j < 8; j++) {
                float2 w = *(const float2 *)(wrow + 2 * j);
                ffma2(acc[j], vv, w);
            }
        }
    }
    float *y = Y + ((size_t)b * N + n) * 16;
#pragma unroll
    for (int j = 0; j < 4; j++)
        *(float4 *)(y + 4 * j) = make_float4(acc[2 * j].x, acc[2 * j].y,
                                             acc[2 * j + 1].x, acc[2 * j + 1].y);
}

// ---------------------------------------------------------------------------
// Generic spiral-conv layer as a gather-SGEMM.
//   C[b, row, :COUT] = sum_s X[b, idx[row,s], :CIN] @ W[s*CIN:(s+1)*CIN, :COUT] + bias
// BM=128 rows per block, BN=COUT, BK=CIN (one spiral step per k-block).
// A is stored to smem DUPLICATED as {x,x} float2 so the inner loop is pure
// fma.rn.f32x2 (acc pairs along n; b-pairs are contiguous floats in Bs).
// If FUSE: the final 128->3 linear (Wf, bf) is applied through smem and the
// 3-channel result written directly (skips the 205MB layer-3 activation).
// ---------------------------------------------------------------------------
template <int CIN, int COUT, int TN, bool FUSE>
__global__ void __launch_bounds__(256)
spiral_layer(const float *__restrict__ X,    // [B,N,CIN]
             const int   *__restrict__ idxg, // [N,S]
             const float *__restrict__ W,    // [S*CIN, COUT]
             const float *__restrict__ bias, // [COUT]
             const float *__restrict__ Wf,   // [COUT,3] (FUSE only)
             const float *__restrict__ bf,   // [3]      (FUSE only)
             float *__restrict__ Y,          // [B,N,COUT] or [B,N,3] if FUSE
             int N) {
    extern __shared__ float sm[];
    float2 *A2  = (float2 *)sm;                       // [CIN][BM] duplicated pairs
    float  *Bs  = sm + 2 * CIN * BM;                  // [CIN][COUT]
    int    *idxs = (int *)(Bs + CIN * COUT);          // [S][BM]
    float  *Wfs = (float *)(idxs + SPI * BM);         // [COUT*3 + 3] (FUSE)

    int tid  = threadIdx.x;
    int b    = blockIdx.y;
    int row0 = blockIdx.x * BM;
    const float *Xb = X + (size_t)b * N * CIN;

    // idx tile (coalesced global read, scattered smem write)
    for (int t = tid; t < SPI * BM; t += 256) {
        int m = t / SPI, s = t % SPI;
        int r = row0 + m;
        if (r >= N) r = N - 1;
        idxs[s * BM + m] = idxg[(size_t)r * SPI + s];
    }
    if (FUSE) {
        for (int t = tid; t < COUT * 3 + 3; t += 256)
            Wfs[t] = (t < COUT * 3) ? Wf[t] : bf[t - COUT * 3];
    }

    int tx = tid & 15, ty = tid >> 4;
    int m0 = ty * TM, n0 = tx * TN;

    float2 acc[TM][TN / 2];
#pragma unroll
    for (int j = 0; j < TN / 2; j++) {
        float2 bv = make_float2(bias[n0 + 2 * j], bias[n0 + 2 * j + 1]);
#pragma unroll
        for (int i = 0; i < TM; i++) acc[i][j] = bv;
    }

    // gather-loader mapping: warp covers 32 rows x half of CIN
    int warp = tid >> 5, lane = tid & 31;
    int mW = (warp & 3) * 32 + lane;
    int kW = (warp >> 2) * (CIN / 2);

    __syncthreads();  // idxs (and Wfs) ready

    for (int s = 0; s < SPI; s++) {
        if (s) __syncthreads();  // previous compute done before overwrite
        // --- gather A tile, duplicated {x,x} ---
        {
            int r = idxs[s * BM + mW];
            const float *src = Xb + (size_t)r * CIN + kW;
#pragma unroll
            for (int q = 0; q < CIN / 8; q++) {
                float4 v = __ldg((const float4 *)(src + 4 * q));
                float2 *d = A2 + (kW + 4 * q) * BM + mW;
                d[0 * BM] = make_float2(v.x, v.x);
                d[1 * BM] = make_float2(v.y, v.y);
                d[2 * BM] = make_float2(v.z, v.z);
                d[3 * BM] = make_float2(v.w, v.w);
            }
        }
        // --- W tile ---
        {
            const float *Wt = W + (size_t)s * CIN * COUT;
#pragma unroll
            for (int t = 4 * tid; t < CIN * COUT; t += 1024)
                *(float4 *)(Bs + t) = __ldg((const float4 *)(Wt + t));
        }
        __syncthreads();
        // --- compute: pure FFMA2 inner loop ---
#pragma unroll 8
        for (int k = 0; k < CIN; k++) {
            float2 a2[TM];
#pragma unroll
            for (int i = 0; i < TM / 2; i++) {
                float4 t4 = *(const float4 *)(A2 + k * BM + m0 + 2 * i);
                a2[2 * i]     = make_float2(t4.x, t4.y);
                a2[2 * i + 1] = make_float2(t4.z, t4.w);
            }
            float2 bb[TN / 2];
            if (TN >= 4) {
#pragma unroll
                for (int j = 0; j < TN / 4; j++) {
                    float4 t4 = *(const float4 *)(Bs + k * COUT + n0 + 4 * j);
                    bb[2 * j]     = make_float2(t4.x, t4.y);
                    bb[2 * j + 1] = make_float2(t4.z, t4.w);
                }
            } else {
                bb[0] = *(const float2 *)(Bs + k * COUT + n0);
            }
#pragma unroll
            for (int i = 0; i < TM; i++)
#pragma unroll
                for (int j = 0; j < TN / 2; j++)
                    ffma2(acc[i][j], a2[i], bb[j]);
        }
    }

    if (!FUSE) {
        float *Yb = Y + (size_t)b * N * COUT;
#pragma unroll
        for (int i = 0; i < TM; i++) {
            int r = row0 + m0 + i;
            if (r < N) {
                float *yr = Yb + (size_t)r * COUT + n0;
                if (TN >= 4) {
#pragma unroll
                    for (int j = 0; j < TN / 4; j++)
                        *(float4 *)(yr + 4 * j) =
                            make_float4(acc[i][2 * j].x, acc[i][2 * j].y,
                                        acc[i][2 * j + 1].x, acc[i][2 * j + 1].y);
                } else {
                    *(float2 *)yr = acc[i][0];
                }
            }
        }
    } else {
        // fused final linear COUT -> 3 through smem
        constexpr int CSTR = COUT + 4;
        __syncthreads();  // everyone done reading A2/Bs
        float *Cs = sm;   // [BM][CSTR], overlaps dead A2/Bs
#pragma unroll
        for (int i = 0; i < TM; i++)
#pragma unroll
            for (int j = 0; j < TN / 4; j++)
                *(float4 *)(Cs + (m0 + i) * CSTR + n0 + 4 * j) =
                    make_float4(acc[i][2 * j].x, acc[i][2 * j].y,
                                acc[i][2 * j + 1].x, acc[i][2 * j + 1].y);
        __syncthreads();
        if (tid < BM) {
            int r = row0 + tid;
            float o0 = Wfs[COUT * 3 + 0];
            float o1 = Wfs[COUT * 3 + 1];
            float o2 = Wfs[COUT * 3 + 2];
            const float *crow = Cs + tid * CSTR;
#pragma unroll 16
            for (int k = 0; k < COUT; k++) {
                float v = crow[k];
                o0 = fmaf(v, Wfs[3 * k + 0], o0);
                o1 = fmaf(v, Wfs[3 * k + 1], o1);
                o2 = fmaf(v, Wfs[3 * k + 2], o2);
            }
            if (r < N) {
                float *o = Y + ((size_t)b * N + r) * 3;
                o[0] = o0; o[1] = o1; o[2] = o2;
            }
        }
    }
}

// ---------------------------------------------------------------------------
// Launch
// ---------------------------------------------------------------------------
extern "C" void kernel_launch(void *const *d_in, const int *in_sizes, int n_in,
                              void *d_out, int out_size) {
    const float *x   = (const float *)d_in[0];
    const int   *idx = (const int *)d_in[1];
    const float *W0  = (const float *)d_in[2];
    const float *b0  = (const float *)d_in[3];
    const float *W1  = (const float *)d_in[4];
    const float *b1  = (const float *)d_in[5];
    const float *W2  = (const float *)d_in[6];
    const float *b2  = (const float *)d_in[7];
    const float *W3  = (const float *)d_in[8];
    const float *b3  = (const float *)d_in[9];
    const float *Wf  = (const float *)d_in[10];
    const float *bf  = (const float *)d_in[11];
    float *out = (float *)d_out;

    int N = in_sizes[1] / SPI;          // spiral_idx has N*S elements
    int B = in_sizes[0] / (N * 3);      // x has B*N*3 elements

    float *bufA, *bufB;
    cudaGetSymbolAddress((void **)&bufA, g_bufA);
    cudaGetSymbolAddress((void **)&bufB, g_bufB);

    dim3 g0((N + 255) / 256, B);
    layer0_kernel<<<g0, 256>>>(x, idx, W0, b0, bufA, N);

    dim3 gl((N + BM - 1) / BM, B);

    size_t sm1 = (size_t)(2 * 16 * BM + 16 * 32 + SPI * BM) * 4;
    spiral_layer<16, 32, 2, false><<<gl, 256, sm1>>>(bufA, idx, W1, b1,
                                                     nullptr, nullptr, bufB, N);

    size_t sm2 = (size_t)(2 * 32 * BM + 32 * 64 + SPI * BM) * 4;
    spiral_layer<32, 64, 4, false><<<gl, 256, sm2>>>(bufB, idx, W2, b2,
                                                     nullptr, nullptr, bufA, N);

    size_t sm3 = (size_t)(2 * 64 * BM + 64 * 128 + SPI * BM + 128 * 3 + 3) * 4;
    cudaFuncSetAttribute(spiral_layer<64, 128, 8, true>,
                         cudaFuncAttributeMaxDynamicSharedMemorySize, (int)sm3);
    spiral_layer<64, 128, 8, true><<<gl, 256, sm3>>>(bufA, idx, W3, b3,
                                                     Wf, bf, out, N);
}

// round 3
// speedup vs baseline: 1.1911x; 1.1911x over previous
#include <cuda_runtime.h>
#include <cstddef>

#define SPI 9          // spiral length
#define BM  128        // rows per block in the GEMM kernels
#define TM  8          // rows per thread (paired in float2 along M)

// ---------------------------------------------------------------------------
// Scratch (ping-pong). Sized for B=8, N=50000.
// ---------------------------------------------------------------------------
__device__ float g_bufA[(size_t)8 * 50000 * 64];
__device__ float g_bufB[(size_t)8 * 50000 * 32];

// Packed fp32x2 FMA: d = a*b + d (lane-wise). 2x fp32 rate vs plain FFMA.
__device__ __forceinline__ void ffma2(float2 &d, const float2 &a, const float2 &b) {
    unsigned long long       &du = reinterpret_cast<unsigned long long &>(d);
    const unsigned long long &au = reinterpret_cast<const unsigned long long &>(a);
    const unsigned long long &bu = reinterpret_cast<const unsigned long long &>(b);
    asm("fma.rn.f32x2 %0, %1, %2, %0;" : "+l"(du) : "l"(au), "l"(bu));
}

// ---------------------------------------------------------------------------
// Layer 0: Cin=3 -> Cout=16.  Thread-per-vertex; W0 (27x16) in smem.
// ---------------------------------------------------------------------------
__global__ void layer0_kernel(const float *__restrict__ X,   // [B,N,3]
                              const int   *__restrict__ idx, // [N,S]
                              const float *__restrict__ W,   // [27,16]
                              const float *__restrict__ bias,// [16]
                              float *__restrict__ Y,         // [B,N,16]
                              int N) {
    __shared__ float Ws[27 * 16];
    __shared__ float bs[16];
    int tid = threadIdx.x;
    for (int t = tid; t < 27 * 16; t += blockDim.x) Ws[t] = W[t];
    if (tid < 16) bs[tid] = bias[tid];
    __syncthreads();

    int n = blockIdx.x * blockDim.x + tid;
    int b = blockIdx.y;
    if (n >= N) return;

    float2 acc[8];
#pragma unroll
    for (int j = 0; j < 8; j++) acc[j] = make_float2(bs[2 * j], bs[2 * j + 1]);

    const float *Xb = X + (size_t)b * N * 3;
#pragma unroll
    for (int s = 0; s < SPI; s++) {
        int r = idx[n * SPI + s];
        float xv[3];
        xv[0] = __ldg(Xb + (size_t)r * 3 + 0);
        xv[1] = __ldg(Xb + (size_t)r * 3 + 1);
        xv[2] = __ldg(Xb + (size_t)r * 3 + 2);
#pragma unroll
        for (int c = 0; c < 3; c++) {
            const float *wrow = Ws + (s * 3 + c) * 16;
            float2 vv = make_float2(xv[c], xv[c]);
#pragma unroll
            for (int j = 0; j < 8; j++) {
                float2 w = *(const float2 *)(wrow + 2 * j);
                ffma2(acc[j], vv, w);
            }
        }
    }
    float *y = Y + ((size_t)b * N + n) * 16;
#pragma unroll
    for (int j = 0; j < 4; j++)
        *(float4 *)(y + 4 * j) = make_float4(acc[2 * j].x, acc[2 * j].y,
                                             acc[2 * j + 1].x, acc[2 * j + 1].y);
}

// ---------------------------------------------------------------------------
// Spiral-conv layer as gather-SGEMM, M-paired FFMA2 micro-kernel.
//   A tile: plain [CIN][BM] floats (a-pairs {a_m,a_m+1} contiguous -> LDS.64)
//   B tile: [CIN][COUT]; b value duplicated {b,b} in registers (ALU movs).
// Per-thread per-k smem traffic: TM*4 + TN*4 bytes (was 12*TM+... duplicated).
// ---------------------------------------------------------------------------
template <int CIN, int COUT, int TN, bool FUSE>
__global__ void __launch_bounds__(256, 2)
spiral_layer(const float *__restrict__ X,    // [B,N,CIN]
             const int   *__restrict__ idxg, // [N,S]
             const float *__restrict__ W,    // [S*CIN, COUT]
             const float *__restrict__ bias, // [COUT]
             const float *__restrict__ Wf,   // [COUT,3] (FUSE only)
             const float *__restrict__ bf,   // [3]      (FUSE only)
             float *__restrict__ Y,          // [B,N,COUT] or [B,N,3] if FUSE
             int N) {
    extern __shared__ float sm[];
    float *As   = sm;                                 // [CIN][BM]
    float *Bs   = sm + CIN * BM;                      // [CIN][COUT]
    int   *idxs = (int *)(Bs + CIN * COUT);           // [S][BM]
    float *Wfs  = (float *)(idxs + SPI * BM);         // [COUT*3 + 3] (FUSE)

    int tid  = threadIdx.x;
    int b    = blockIdx.y;
    int row0 = blockIdx.x * BM;
    const float *Xb = X + (size_t)b * N * CIN;

    // idx tile
    for (int t = tid; t < SPI * BM; t += 256) {
        int m = t / SPI, s = t % SPI;
        int r = row0 + m;
        if (r >= N) r = N - 1;
        idxs[s * BM + m] = idxg[(size_t)r * SPI + s];
    }
    if (FUSE) {
        for (int t = tid; t < COUT * 3 + 3; t += 256)
            Wfs[t] = (t < COUT * 3) ? Wf[t] : bf[t - COUT * 3];
    }

    int tx = tid & 15, ty = tid >> 4;
    int m0 = ty * TM, n0 = tx * TN;

    // acc[i][j]: rows (m0+2i, m0+2i+1), column n0+j
    float2 acc[TM / 2][TN];
#pragma unroll
    for (int j = 0; j < TN; j++) {
        float bv = bias[n0 + j];
#pragma unroll
        for (int i = 0; i < TM / 2; i++) acc[i][j] = make_float2(bv, bv);
    }

    // gather-loader mapping: warp covers 32 rows x half of CIN
    int warp = tid >> 5, lane = tid & 31;
    int mW = (warp & 3) * 32 + lane;
    int kW = (warp >> 2) * (CIN / 2);

    __syncthreads();  // idxs (and Wfs) ready

    for (int s = 0; s < SPI; s++) {
        if (s) __syncthreads();
        // --- gather A tile (plain floats, [k][BM]) ---
        {
            int r = idxs[s * BM + mW];
            const float *src = Xb + (size_t)r * CIN + kW;
#pragma unroll
            for (int q = 0; q < CIN / 8; q++) {
                float4 v = __ldg((const float4 *)(src + 4 * q));
                float *d = As + (kW + 4 * q) * BM + mW;
                d[0 * BM] = v.x;
                d[1 * BM] = v.y;
                d[2 * BM] = v.z;
                d[3 * BM] = v.w;
            }
        }
        // --- W tile ---
        {
            const float *Wt = W + (size_t)s * CIN * COUT;
#pragma unroll
            for (int t = 4 * tid; t < CIN * COUT; t += 1024)
                *(float4 *)(Bs + t) = __ldg((const float4 *)(Wt + t));
        }
        __syncthreads();
        // --- compute ---
#pragma unroll 4
        for (int k = 0; k < CIN; k++) {
            // a-pairs: contiguous rows, one 64-bit LDS each
            float2 a2[TM / 2];
#pragma unroll
            for (int i = 0; i < TM / 2; i++)
                a2[i] = *(const float2 *)(As + k * BM + m0 + 2 * i);
            // b values: plain loads then register-duplicate
            float2 b2[TN];
            if (TN >= 4) {
#pragma unroll
                for (int j = 0; j < TN / 4; j++) {
                    float4 t4 = *(const float4 *)(Bs + k * COUT + n0 + 4 * j);
                    b2[4 * j + 0] = make_float2(t4.x, t4.x);
                    b2[4 * j + 1] = make_float2(t4.y, t4.y);
                    b2[4 * j + 2] = make_float2(t4.z, t4.z);
                    b2[4 * j + 3] = make_float2(t4.w, t4.w);
                }
            } else {
                float2 t2 = *(const float2 *)(Bs + k * COUT + n0);
                b2[0] = make_float2(t2.x, t2.x);
                b2[1] = make_float2(t2.y, t2.y);
            }
#pragma unroll
            for (int i = 0; i < TM / 2; i++)
#pragma unroll
                for (int j = 0; j < TN; j++)
                    ffma2(acc[i][j], a2[i], b2[j]);
        }
    }

    if (!FUSE) {
        float *Yb = Y + (size_t)b * N * COUT;
#pragma unroll
        for (int i = 0; i < TM / 2; i++) {
            int r0 = row0 + m0 + 2 * i;
            if (r0 < N) {
                float *yr = Yb + (size_t)r0 * COUT + n0;
                if (TN >= 4) {
#pragma unroll
                    for (int j = 0; j < TN / 4; j++)
                        *(float4 *)(yr + 4 * j) =
                            make_float4(acc[i][4 * j].x, acc[i][4 * j + 1].x,
                                        acc[i][4 * j + 2].x, acc[i][4 * j + 3].x);
                } else {
                    *(float2 *)yr = make_float2(acc[i][0].x, acc[i][1].x);
                }
            }
            int r1 = r0 + 1;
            if (r1 < N) {
                float *yr = Yb + (size_t)r1 * COUT + n0;
                if (TN >= 4) {
#pragma unroll
                    for (int j = 0; j < TN / 4; j++)
                        *(float4 *)(yr + 4 * j) =
                            make_float4(acc[i][4 * j].y, acc[i][4 * j + 1].y,
                                        acc[i][4 * j + 2].y, acc[i][4 * j + 3].y);
                } else {
                    *(float2 *)yr = make_float2(acc[i][0].y, acc[i][1].y);
                }
            }
        }
    } else {
        // fused final linear COUT -> 3 through smem
        constexpr int CSTR = COUT + 4;
        __syncthreads();  // everyone done reading As/Bs
        float *Cs = sm;   // [BM][CSTR], overlaps dead As/Bs/idxs (not Wfs)
#pragma unroll
        for (int i = 0; i < TM / 2; i++) {
#pragma unroll
            for (int j = 0; j < TN / 4; j++) {
                *(float4 *)(Cs + (m0 + 2 * i) * CSTR + n0 + 4 * j) =
                    make_float4(acc[i][4 * j].x, acc[i][4 * j + 1].x,
                                acc[i][4 * j + 2].x, acc[i][4 * j + 3].x);
                *(float4 *)(Cs + (m0 + 2 * i + 1) * CSTR + n0 + 4 * j) =
                    make_float4(acc[i][4 * j].y, acc[i][4 * j + 1].y,
                                acc[i][4 * j + 2].y, acc[i][4 * j + 3].y);
            }
        }
        __syncthreads();
        if (tid < BM) {
            int r = row0 + tid;
            float o0 = Wfs[COUT * 3 + 0];
            float o1 = Wfs[COUT * 3 + 1];
            float o2 = Wfs[COUT * 3 + 2];
            const float *crow = Cs + tid * CSTR;
#pragma unroll 16
            for (int k = 0; k < COUT; k++) {
                float v = crow[k];
                o0 = fmaf(v, Wfs[3 * k + 0], o0);
                o1 = fmaf(v, Wfs[3 * k + 1], o1);
                o2 = fmaf(v, Wfs[3 * k + 2], o2);
            }
            if (r < N) {
                float *o = Y + ((size_t)b * N + r) * 3;
                o[0] = o0; o[1] = o1; o[2] = o2;
            }
        }
    }
}

// ---------------------------------------------------------------------------
// Launch
// ---------------------------------------------------------------------------
extern "C" void kernel_launch(void *const *d_in, const int *in_sizes, int n_in,
                              void *d_out, int out_size) {
    const float *x   = (const float *)d_in[0];
    const int   *idx = (const int *)d_in[1];
    const float *W0  = (const float *)d_in[2];
    const float *b0  = (const float *)d_in[3];
    const float *W1  = (const float *)d_in[4];
    const float *b1  = (const float *)d_in[5];
    const float *W2  = (const float *)d_in[6];
    const float *b2  = (const float *)d_in[7];
    const float *W3  = (const float *)d_in[8];
    const float *b3  = (const float *)d_in[9];
    const float *Wf  = (const float *)d_in[10];
    const float *bf  = (const float *)d_in[11];
    float *out = (float *)d_out;

    int N = in_sizes[1] / SPI;
    int B = in_sizes[0] / (N * 3);

    float *bufA, *bufB;
    cudaGetSymbolAddress((void **)&bufA, g_bufA);
    cudaGetSymbolAddress((void **)&bufB, g_bufB);

    dim3 g0((N + 255) / 256, B);
    layer0_kernel<<<g0, 256>>>(x, idx, W0, b0, bufA, N);

    dim3 gl((N + BM - 1) / BM, B);

    size_t sm1 = (size_t)(16 * BM + 16 * 32 + SPI * BM) * 4;
    spiral_layer<16, 32, 2, false><<<gl, 256, sm1>>>(bufA, idx, W1, b1,
                                                     nullptr, nullptr, bufB, N);

    size_t sm2 = (size_t)(32 * BM + 32 * 64 + SPI * BM) * 4;
    spiral_layer<32, 64, 4, false><<<gl, 256, sm2>>>(bufB, idx, W2, b2,
                                                     nullptr, nullptr, bufA, N);

    size_t sm3 = (size_t)(64 * BM + 64 * 128 + SPI * BM + 128 * 3 + 3) * 4;
    // FUSE scratch Cs = BM*(COUT+4) floats = 67584B <= sm3? ensure max:
    size_t sm3f = (size_t)BM * (128 + 4) * 4 + ((size_t)(128 * 3 + 3)) * 4 +
                  (size_t)(SPI * BM) * 4;  // upper bound, keeps Wfs region valid
    if (sm3f > sm3) sm3 = sm3f;
    cudaFuncSetAttribute(spiral_layer<64, 128, 8, true>,
                         cudaFuncAttributeMaxDynamicSharedMemorySize, (int)sm3);
    spiral_layer<64, 128, 8, true><<<gl, 256, sm3>>>(bufA, idx, W3, b3,
                                                     Wf, bf, out, N);
}

// round 4
// speedup vs baseline: 1.3104x; 1.1001x over previous
#include <cuda_runtime.h>
#include <cstddef>

#define SPI 9          // spiral length
#define BM  128        // rows per block in the GEMM kernels
#define TM  8          // rows per thread (paired in float2 along M)

__device__ float g_bufA[(size_t)8 * 50000 * 64];
__device__ float g_bufB[(size_t)8 * 50000 * 32];

// Packed fp32x2 FMA: d = a*b + d (lane-wise). 2x fp32 rate vs plain FFMA.
__device__ __forceinline__ void ffma2(float2 &d, const float2 &a, const float2 &b) {
    unsigned long long       &du = reinterpret_cast<unsigned long long &>(d);
    const unsigned long long &au = reinterpret_cast<const unsigned long long &>(a);
    const unsigned long long &bu = reinterpret_cast<const unsigned long long &>(b);
    asm("fma.rn.f32x2 %0, %1, %2, %0;" : "+l"(du) : "l"(au), "l"(bu));
}

// ---------------------------------------------------------------------------
// Layer 0: Cin=3 -> Cout=16.  Thread-per-vertex; W0 (27x16) in smem.
// ---------------------------------------------------------------------------
__global__ void layer0_kernel(const float *__restrict__ X,
                              const int   *__restrict__ idx,
                              const float *__restrict__ W,
                              const float *__restrict__ bias,
                              float *__restrict__ Y,
                              int N) {
    __shared__ float Ws[27 * 16];
    __shared__ float bs[16];
    int tid = threadIdx.x;
    for (int t = tid; t < 27 * 16; t += blockDim.x) Ws[t] = W[t];
    if (tid < 16) bs[tid] = bias[tid];
    __syncthreads();

    int n = blockIdx.x * blockDim.x + tid;
    int b = blockIdx.y;
    if (n >= N) return;

    float2 acc[8];
#pragma unroll
    for (int j = 0; j < 8; j++) acc[j] = make_float2(bs[2 * j], bs[2 * j + 1]);

    const float *Xb = X + (size_t)b * N * 3;
#pragma unroll
    for (int s = 0; s < SPI; s++) {
        int r = idx[n * SPI + s];
        float xv[3];
        xv[0] = __ldg(Xb + (size_t)r * 3 + 0);
        xv[1] = __ldg(Xb + (size_t)r * 3 + 1);
        xv[2] = __ldg(Xb + (size_t)r * 3 + 2);
#pragma unroll
        for (int c = 0; c < 3; c++) {
            const float *wrow = Ws + (s * 3 + c) * 16;
            float2 vv = make_float2(xv[c], xv[c]);
#pragma unroll
            for (int j = 0; j < 8; j++) {
                float2 w = *(const float2 *)(wrow + 2 * j);
                ffma2(acc[j], vv, w);
            }
        }
    }
    float *y = Y + ((size_t)b * N + n) * 16;
#pragma unroll
    for (int j = 0; j < 4; j++)
        *(float4 *)(y + 4 * j) = make_float4(acc[2 * j].x, acc[2 * j].y,
                                             acc[2 * j + 1].x, acc[2 * j + 1].y);
}

// ---------------------------------------------------------------------------
// Spiral-conv layer as gather-SGEMM, M-paired FFMA2 micro-kernel.
//   A tile [CIN][BM] plain floats; per-k a-loads = 2x LDS.128 (broadcast, CF).
//   B tile [CIN][COUT]; thread's TN cols split into NG groups of 4 at stride
//   COUT/NG so each b-LDS.128 is 16 lanes x contiguous 16B (conflict-free).
// ---------------------------------------------------------------------------
template <int CIN, int COUT, int TN, bool FUSE>
__global__ void __launch_bounds__(256, 2)
spiral_layer(const float *__restrict__ X,
             const int   *__restrict__ idxg,
             const float *__restrict__ W,
             const float *__restrict__ bias,
             const float *__restrict__ Wf,
             const float *__restrict__ bf,
             float *__restrict__ Y,
             int N) {
    extern __shared__ float sm[];
    float *As   = sm;                                 // [CIN][BM]
    float *Bs   = sm + CIN * BM;                      // [CIN][COUT]
    int   *idxs = (int *)(Bs + CIN * COUT);           // [S][BM]
    float *Wfs  = (float *)(idxs + SPI * BM);         // [COUT*3+3] (FUSE)

    constexpr int NG     = (TN >= 4) ? TN / 4 : 1;    // groups of 4 cols
    constexpr int GSTRIDE = COUT / NG;                // column stride between groups

    int tid  = threadIdx.x;
    int b    = blockIdx.y;
    int row0 = blockIdx.x * BM;
    const float *Xb = X + (size_t)b * N * CIN;

    for (int t = tid; t < SPI * BM; t += 256) {
        int m = t / SPI, s = t % SPI;
        int r = row0 + m;
        if (r >= N) r = N - 1;
        idxs[s * BM + m] = idxg[(size_t)r * SPI + s];
    }
    if (FUSE) {
        for (int t = tid; t < COUT * 3 + 3; t += 256)
            Wfs[t] = (t < COUT * 3) ? Wf[t] : bf[t - COUT * 3];
    }

    int tx = tid & 15, ty = tid >> 4;
    int m0 = ty * TM;
    int n0 = tx * ((TN >= 4) ? 4 : TN);   // base col within group 0

    // acc[i][g*4+c]: rows (m0+2i, m0+2i+1), column g*GSTRIDE + n0 + c
    float2 acc[TM / 2][TN];
#pragma unroll
    for (int g = 0; g < NG; g++)
#pragma unroll
        for (int c = 0; c < ((TN >= 4) ? 4 : TN); c++) {
            float bv = bias[g * GSTRIDE + n0 + c];
#pragma unroll
            for (int i = 0; i < TM / 2; i++)
                acc[i][g * 4 + c] = make_float2(bv, bv);
        }

    int warp = tid >> 5, lane = tid & 31;
    int mW = (warp & 3) * 32 + lane;
    int kW = (warp >> 2) * (CIN / 2);

    __syncthreads();

    for (int s = 0; s < SPI; s++) {
        if (s) __syncthreads();
        // --- gather A tile ---
        {
            int r = idxs[s * BM + mW];
            const float *src = Xb + (size_t)r * CIN + kW;
#pragma unroll
            for (int q = 0; q < CIN / 8; q++) {
                float4 v = __ldg((const float4 *)(src + 4 * q));
                float *d = As + (kW + 4 * q) * BM + mW;
                d[0 * BM] = v.x;
                d[1 * BM] = v.y;
                d[2 * BM] = v.z;
                d[3 * BM] = v.w;
            }
        }
        // --- W tile ---
        {
            const float *Wt = W + (size_t)s * CIN * COUT;
#pragma unroll
            for (int t = 4 * tid; t < CIN * COUT; t += 1024)
                *(float4 *)(Bs + t) = __ldg((const float4 *)(Wt + t));
        }
        __syncthreads();
        // --- compute ---
#pragma unroll 4
        for (int k = 0; k < CIN; k++) {
            // a: two float4 loads (rows m0..m0+7), broadcast within warp
            float2 a2[TM / 2];
            {
                float4 v0 = *(const float4 *)(As + k * BM + m0);
                float4 v1 = *(const float4 *)(As + k * BM + m0 + 4);
                a2[0] = make_float2(v0.x, v0.y);
                a2[1] = make_float2(v0.z, v0.w);
                a2[2] = make_float2(v1.x, v1.y);
                a2[3] = make_float2(v1.z, v1.w);
            }
            // b: NG conflict-free float4 loads, duplicated in registers
            float2 b2[TN];
            if (TN >= 4) {
#pragma unroll
                for (int g = 0; g < NG; g++) {
                    float4 t4 = *(const float4 *)(Bs + k * COUT + g * GSTRIDE + n0);
                    b2[4 * g + 0] = make_float2(t4.x, t4.x);
                    b2[4 * g + 1] = make_float2(t4.y, t4.y);
                    b2[4 * g + 2] = make_float2(t4.z, t4.z);
                    b2[4 * g + 3] = make_float2(t4.w, t4.w);
                }
            } else {
                float2 t2 = *(const float2 *)(Bs + k * COUT + n0);
                b2[0] = make_float2(t2.x, t2.x);
                b2[1] = make_float2(t2.y, t2.y);
            }
#pragma unroll
            for (int i = 0; i < TM / 2; i++)
#pragma unroll
                for (int j = 0; j < TN; j++)
                    ffma2(acc[i][j], a2[i], b2[j]);
        }
    }

    if (!FUSE) {
        float *Yb = Y + (size_t)b * N * COUT;
#pragma unroll
        for (int i = 0; i < TM / 2; i++) {
            int r0 = row0 + m0 + 2 * i;
            int r1 = r0 + 1;
            if (TN >= 4) {
#pragma unroll
                for (int g = 0; g < NG; g++) {
                    int col = g * GSTRIDE + n0;
                    if (r0 < N)
                        *(float4 *)(Yb + (size_t)r0 * COUT + col) =
                            make_float4(acc[i][4 * g].x, acc[i][4 * g + 1].x,
                                        acc[i][4 * g + 2].x, acc[i][4 * g + 3].x);
                    if (r1 < N)
                        *(float4 *)(Yb + (size_t)r1 * COUT + col) =
                            make_float4(acc[i][4 * g].y, acc[i][4 * g + 1].y,
                                        acc[i][4 * g + 2].y, acc[i][4 * g + 3].y);
                }
            } else {
                if (r0 < N)
                    *(float2 *)(Yb + (size_t)r0 * COUT + n0) =
                        make_float2(acc[i][0].x, acc[i][1].x);
                if (r1 < N)
                    *(float2 *)(Yb + (size_t)r1 * COUT + n0) =
                        make_float2(acc[i][0].y, acc[i][1].y);
            }
        }
    } else {
        // fused final linear COUT -> 3 through smem
        constexpr int CSTR = COUT + 4;
        __syncthreads();
        float *Cs = sm;   // [BM][CSTR], overlaps dead As/Bs/idxs (not Wfs)
#pragma unroll
        for (int i = 0; i < TM / 2; i++) {
#pragma unroll
            for (int g = 0; g < NG; g++) {
                int col = g * GSTRIDE + n0;
                *(float4 *)(Cs + (m0 + 2 * i) * CSTR + col) =
                    make_float4(acc[i][4 * g].x, acc[i][4 * g + 1].x,
                                acc[i][4 * g + 2].x, acc[i][4 * g + 3].x);
                *(float4 *)(Cs + (m0 + 2 * i + 1) * CSTR + col) =
                    make_float4(acc[i][4 * g].y, acc[i][4 * g + 1].y,
                                acc[i][4 * g + 2].y, acc[i][4 * g + 3].y);
            }
        }
        __syncthreads();
        if (tid < BM) {
            int r = row0 + tid;
            float o0 = Wfs[COUT * 3 + 0];
            float o1 = Wfs[COUT * 3 + 1];
            float o2 = Wfs[COUT * 3 + 2];
            const float *crow = Cs + tid * CSTR;
#pragma unroll 16
            for (int k = 0; k < COUT; k++) {
                float v = crow[k];
                o0 = fmaf(v, Wfs[3 * k + 0], o0);
                o1 = fmaf(v, Wfs[3 * k + 1], o1);
                o2 = fmaf(v, Wfs[3 * k + 2], o2);
            }
            if (r < N) {
                float *o = Y + ((size_t)b * N + r) * 3;
                o[0] = o0; o[1] = o1; o[2] = o2;
            }
        }
    }
}

// ---------------------------------------------------------------------------
extern "C" void kernel_launch(void *const *d_in, const int *in_sizes, int n_in,
                              void *d_out, int out_size) {
    const float *x   = (const float *)d_in[0];
    const int   *idx = (const int *)d_in[1];
    const float *W0  = (const float *)d_in[2];
    const float *b0  = (const float *)d_in[3];
    const float *W1  = (const float *)d_in[4];
    const float *b1  = (const float *)d_in[5];
    const float *W2  = (const float *)d_in[6];
    const float *b2  = (const float *)d_in[7];
    const float *W3  = (const float *)d_in[8];
    const float *b3  = (const float *)d_in[9];
    const float *Wf  = (const float *)d_in[10];
    const float *bf  = (const float *)d_in[11];
    float *out = (float *)d_out;

    int N = in_sizes[1] / SPI;
    int B = in_sizes[0] / (N * 3);

    float *bufA, *bufB;
    cudaGetSymbolAddress((void **)&bufA, g_bufA);
    cudaGetSymbolAddress((void **)&bufB, g_bufB);

    dim3 g0((N + 255) / 256, B);
    layer0_kernel<<<g0, 256>>>(x, idx, W0, b0, bufA, N);

    dim3 gl((N + BM - 1) / BM, B);

    size_t sm1 = (size_t)(16 * BM + 16 * 32 + SPI * BM) * 4;
    spiral_layer<16, 32, 2, false><<<gl, 256, sm1>>>(bufA, idx, W1, b1,
                                                     nullptr, nullptr, bufB, N);

    size_t sm2 = (size_t)(32 * BM + 32 * 64 + SPI * BM) * 4;
    spiral_layer<32, 64, 4, false><<<gl, 256, sm2>>>(bufB, idx, W2, b2,
                                                     nullptr, nullptr, bufA, N);

    size_t sm3 = (size_t)(64 * BM + 64 * 128 + SPI * BM + 128 * 3 + 3) * 4;
    size_t sm3f = (size_t)BM * (128 + 4) * 4 + ((size_t)(128 * 3 + 3)) * 4 +
                  (size_t)(SPI * BM) * 4;
    if (sm3f > sm3) sm3 = sm3f;
    cudaFuncSetAttribute(spiral_layer<64, 128, 8, true>,
                         cudaFuncAttributeMaxDynamicSharedMemorySize, (int)sm3);
    spiral_layer<64, 128, 8, true><<<gl, 256, sm3>>>(bufA, idx, W3, b3,
                                                     Wf, bf, out, N);
}

// round 6
// speedup vs baseline: 1.8131x; 1.3836x over previous
#include <cuda_runtime.h>
#include <cuda_bf16.h>
#include <cstddef>
#include <cstdint>

#define SPI 9
#define BM  128
#define TM  8

__device__ float g_bufA[(size_t)8 * 50000 * 64];
__device__ float g_bufB[(size_t)8 * 50000 * 32];
// Pre-transposed, bf16-split, pre-swizzled W3: [9][n=128][k=64] bf16, 16KB per s
__device__ __nv_bfloat16 g_WtHi[9 * 128 * 64];
__device__ __nv_bfloat16 g_WtLo[9 * 128 * 64];

__device__ __forceinline__ void ffma2(float2 &d, const float2 &a, const float2 &b) {
    unsigned long long       &du = reinterpret_cast<unsigned long long &>(d);
    const unsigned long long &au = reinterpret_cast<const unsigned long long &>(a);
    const unsigned long long &bu = reinterpret_cast<const unsigned long long &>(b);
    asm("fma.rn.f32x2 %0, %1, %2, %0;" : "+l"(du) : "l"(au), "l"(bu));
}

__device__ __forceinline__ uint32_t smem_u32(const void *p) {
    uint32_t a;
    asm("{ .reg .u64 t; cvta.to.shared.u64 t, %1; cvt.u32.u64 %0, t; }" : "=r"(a) : "l"(p));
    return a;
}
#define SMEM_SWIZZLE_128B(o) ((o) ^ (((o) >> 3) & 0x70))

__device__ __forceinline__ void ldmx4(uint32_t &r0, uint32_t &r1, uint32_t &r2,
                                      uint32_t &r3, uint32_t addr) {
    asm volatile("ldmatrix.sync.aligned.m8n8.x4.shared.b16 {%0,%1,%2,%3}, [%4];"
                 : "=r"(r0), "=r"(r1), "=r"(r2), "=r"(r3) : "r"(addr));
}
__device__ __forceinline__ void mma16816(float *c, const uint32_t *a,
                                         uint32_t b0, uint32_t b1) {
    asm volatile("mma.sync.aligned.m16n8k16.row.col.f32.bf16.bf16.f32 "
                 "{%0,%1,%2,%3}, {%4,%5,%6,%7}, {%8,%9}, {%0,%1,%2,%3};"
                 : "+f"(c[0]), "+f"(c[1]), "+f"(c[2]), "+f"(c[3])
                 : "r"(a[0]), "r"(a[1]), "r"(a[2]), "r"(a[3]), "r"(b0), "r"(b1));
}

// ---------------------------------------------------------------------------
// Layer 0 (FFMA2 path)
// ---------------------------------------------------------------------------
__global__ void layer0_kernel(const float *__restrict__ X, const int *__restrict__ idx,
                              const float *__restrict__ W, const float *__restrict__ bias,
                              float *__restrict__ Y, int N) {
    __shared__ float Ws[27 * 16];
    __shared__ float bs[16];
    int tid = threadIdx.x;
    for (int t = tid; t < 27 * 16; t += blockDim.x) Ws[t] = W[t];
    if (tid < 16) bs[tid] = bias[tid];
    __syncthreads();

    int n = blockIdx.x * blockDim.x + tid;
    int b = blockIdx.y;
    if (n >= N) return;

    float2 acc[8];
#pragma unroll
    for (int j = 0; j < 8; j++) acc[j] = make_float2(bs[2 * j], bs[2 * j + 1]);

    const float *Xb = X + (size_t)b * N * 3;
#pragma unroll
    for (int s = 0; s < SPI; s++) {
        int r = idx[n * SPI + s];
        float xv[3];
        xv[0] = __ldg(Xb + (size_t)r * 3 + 0);
        xv[1] = __ldg(Xb + (size_t)r * 3 + 1);
        xv[2] = __ldg(Xb + (size_t)r * 3 + 2);
#pragma unroll
        for (int c = 0; c < 3; c++) {
            const float *wrow = Ws + (s * 3 + c) * 16;
            float2 vv = make_float2(xv[c], xv[c]);
#pragma unroll
            for (int j = 0; j < 8; j++) {
                float2 w = *(const float2 *)(wrow + 2 * j);
                ffma2(acc[j], vv, w);
            }
        }
    }
    float *y = Y + ((size_t)b * N + n) * 16;
#pragma unroll
    for (int j = 0; j < 4; j++)
        *(float4 *)(y + 4 * j) = make_float4(acc[2 * j].x, acc[2 * j].y,
                                             acc[2 * j + 1].x, acc[2 * j + 1].y);
}

// ---------------------------------------------------------------------------
// Layers 1-2 (FFMA2 path, unchanged)
// ---------------------------------------------------------------------------
template <int CIN, int COUT, int TN>
__global__ void __launch_bounds__(256, 2)
spiral_layer(const float *__restrict__ X, const int *__restrict__ idxg,
             const float *__restrict__ W, const float *__restrict__ bias,
             float *__restrict__ Y, int N) {
    extern __shared__ float sm[];
    float *As   = sm;
    float *Bs   = sm + CIN * BM;
    int   *idxs = (int *)(Bs + CIN * COUT);

    constexpr int NG = (TN >= 4) ? TN / 4 : 1;
    constexpr int GSTRIDE = COUT / NG;

    int tid  = threadIdx.x;
    int b    = blockIdx.y;
    int row0 = blockIdx.x * BM;
    const float *Xb = X + (size_t)b * N * CIN;

    for (int t = tid; t < SPI * BM; t += 256) {
        int m = t / SPI, s = t % SPI;
        int r = row0 + m;
        if (r >= N) r = N - 1;
        idxs[s * BM + m] = idxg[(size_t)r * SPI + s];
    }

    int tx = tid & 15, ty = tid >> 4;
    int m0 = ty * TM;
    int n0 = tx * ((TN >= 4) ? 4 : TN);

    float2 acc[TM / 2][TN];
#pragma unroll
    for (int g = 0; g < NG; g++)
#pragma unroll
        for (int c = 0; c < ((TN >= 4) ? 4 : TN); c++) {
            float bv = bias[g * GSTRIDE + n0 + c];
#pragma unroll
            for (int i = 0; i < TM / 2; i++) acc[i][g * 4 + c] = make_float2(bv, bv);
        }

    int warp = tid >> 5, lane = tid & 31;
    int mW = (warp & 3) * 32 + lane;
    int kW = (warp >> 2) * (CIN / 2);

    __syncthreads();

    for (int s = 0; s < SPI; s++) {
        if (s) __syncthreads();
        {
            int r = idxs[s * BM + mW];
            const float *src = Xb + (size_t)r * CIN + kW;
#pragma unroll
            for (int q = 0; q < CIN / 8; q++) {
                float4 v = __ldg((const float4 *)(src + 4 * q));
                float *d = As + (kW + 4 * q) * BM + mW;
                d[0 * BM] = v.x; d[1 * BM] = v.y; d[2 * BM] = v.z; d[3 * BM] = v.w;
            }
        }
        {
            const float *Wt = W + (size_t)s * CIN * COUT;
#pragma unroll
            for (int t = 4 * tid; t < CIN * COUT; t += 1024)
                *(float4 *)(Bs + t) = __ldg((const float4 *)(Wt + t));
        }
        __syncthreads();
#pragma unroll 4
        for (int k = 0; k < CIN; k++) {
            float2 a2[TM / 2];
            {
                float4 v0 = *(const float4 *)(As + k * BM + m0);
                float4 v1 = *(const float4 *)(As + k * BM + m0 + 4);
                a2[0] = make_float2(v0.x, v0.y);
                a2[1] = make_float2(v0.z, v0.w);
                a2[2] = make_float2(v1.x, v1.y);
                a2[3] = make_float2(v1.z, v1.w);
            }
            float2 b2[TN];
            if (TN >= 4) {
#pragma unroll
                for (int g = 0; g < NG; g++) {
                    float4 t4 = *(const float4 *)(Bs + k * COUT + g * GSTRIDE + n0);
                    b2[4 * g + 0] = make_float2(t4.x, t4.x);
                    b2[4 * g + 1] = make_float2(t4.y, t4.y);
                    b2[4 * g + 2] = make_float2(t4.z, t4.z);
                    b2[4 * g + 3] = make_float2(t4.w, t4.w);
                }
            } else {
                float2 t2 = *(const float2 *)(Bs + k * COUT + n0);
                b2[0] = make_float2(t2.x, t2.x);
                b2[1] = make_float2(t2.y, t2.y);
            }
#pragma unroll
            for (int i = 0; i < TM / 2; i++)
#pragma unroll
                for (int j = 0; j < TN; j++) ffma2(acc[i][j], a2[i], b2[j]);
        }
    }

    float *Yb = Y + (size_t)b * N * COUT;
#pragma unroll
    for (int i = 0; i < TM / 2; i++) {
        int r0 = row0 + m0 + 2 * i;
        int r1 = r0 + 1;
        if (TN >= 4) {
#pragma unroll
            for (int g = 0; g < NG; g++) {
                int col = g * GSTRIDE + n0;
                if (r0 < N)
                    *(float4 *)(Yb + (size_t)r0 * COUT + col) =
                        make_float4(acc[i][4 * g].x, acc[i][4 * g + 1].x,
                                    acc[i][4 * g + 2].x, acc[i][4 * g + 3].x);
                if (r1 < N)
                    *(float4 *)(Yb + (size_t)r1 * COUT + col) =
                        make_float4(acc[i][4 * g].y, acc[i][4 * g + 1].y,
                                    acc[i][4 * g + 2].y, acc[i][4 * g + 3].y);
            }
        } else {
            if (r0 < N)
                *(float2 *)(Yb + (size_t)r0 * COUT + n0) = make_float2(acc[i][0].x, acc[i][1].x);
            if (r1 < N)
                *(float2 *)(Yb + (size_t)r1 * COUT + n0) = make_float2(acc[i][0].y, acc[i][1].y);
        }
    }
}

// ---------------------------------------------------------------------------
// W3 prep: transpose [576,128] -> per-s [n=128][k=64] bf16 hi/lo, pre-swizzled.
// ---------------------------------------------------------------------------
__global__ void prep_wt_kernel(const float *__restrict__ W3) {
    int s = blockIdx.x;          // 0..8
    int n = threadIdx.x;         // 0..127
    char *dstH = (char *)g_WtHi + (size_t)s * 16384;
    char *dstL = (char *)g_WtLo + (size_t)s * 16384;
    for (int k = 0; k < 64; k++) {
        float w = __ldg(W3 + (size_t)(s * 64 + k) * 128 + n);
        __nv_bfloat16 hi = __float2bfloat16_rn(w);
        __nv_bfloat16 lo = __float2bfloat16_rn(w - __bfloat162float(hi));
        uint32_t off = SMEM_SWIZZLE_128B((uint32_t)(n * 128 + k * 2));
        *(__nv_bfloat16 *)(dstH + off) = hi;
        *(__nv_bfloat16 *)(dstL + off) = lo;
    }
}

// ---------------------------------------------------------------------------
// Layer 3 + fused final linear via mma.sync bf16x3 split (sm_100-baseline PTX).
// Block: 128x128 output, 8 warps as 4(M) x 2(N); warp tile 32x64.
// ---------------------------------------------------------------------------
#define L3_AHI   0
#define L3_ALO   16384
#define L3_BHI   32768
#define L3_BLO   49152
#define L3_IDX   65536            // 9*128*4 = 4608 -> ends 70144
#define L3_WF    70144            // Wf 384 | bf 3 | pad 1 | b3 128 floats
#define L3_SMEM  72256
#define CSTR     132

__global__ void __launch_bounds__(256, 2)
layer3_mma(const float *__restrict__ X,     // [B,N,64]
           const int   *__restrict__ idxg,  // [N,9]
           const float *__restrict__ b3,    // [128]
           const float *__restrict__ Wf,    // [128,3]
           const float *__restrict__ bf,    // [3]
           float *__restrict__ out,         // [B,N,3]
           int N) {
    extern __shared__ __align__(1024) char smc[];
    uint32_t sb = smem_u32(smc);
    int tid = threadIdx.x, wid = tid >> 5, lane = tid & 31;
    int b = blockIdx.y, row0 = blockIdx.x * BM;
    int warpM = wid >> 1, warpN = wid & 1;

    int *idxs = (int *)(smc + L3_IDX);
    for (int t = tid; t < SPI * BM; t += 256) {
        int m = t / SPI, s = t % SPI;
        int r = row0 + m;
        if (r >= N) r = N - 1;
        idxs[s * BM + m] = idxg[(size_t)r * SPI + s];
    }
    float *Wfs = (float *)(smc + L3_WF);
    for (int t = tid; t < 384; t += 256) Wfs[t] = Wf[t];
    if (tid < 3)   Wfs[384 + tid] = bf[tid];
    if (tid < 128) Wfs[388 + tid] = b3[tid];

    // accumulators: 2 m-tiles x 8 n-frags x 4 f32
    float acc[2][8][4];
#pragma unroll
    for (int mt = 0; mt < 2; mt++)
#pragma unroll
        for (int nf = 0; nf < 8; nf++)
#pragma unroll
            for (int c = 0; c < 4; c++) acc[mt][nf][c] = 0.0f;

    const float *Xb = X + (size_t)b * N * 64;
    int grow = tid >> 1, ghalf = tid & 1;

    // ldmatrix lane address components (same pattern for A and B tiles)
    uint32_t lm_row  = (uint32_t)(lane & 15);
    uint32_t lm_half = (uint32_t)(lane >> 4) << 4;   // 0 or 16 bytes

    __syncthreads();

    for (int s = 0; s < SPI; s++) {
        if (s) __syncthreads();
        // --- gather + bf16 split A tile ([row][64 bf16] = 128B rows, SW128) ---
        {
            int r = idxs[s * BM + grow];
            const float *src = Xb + (size_t)r * 64 + ghalf * 32;
            char *aH = smc + L3_AHI, *aL = smc + L3_ALO;
#pragma unroll
            for (int q = 0; q < 8; q++) {
                float4 v = __ldg((const float4 *)(src + 4 * q));
                __nv_bfloat162 h0 = __float22bfloat162_rn(make_float2(v.x, v.y));
                __nv_bfloat162 h1 = __float22bfloat162_rn(make_float2(v.z, v.w));
                float2 f0 = __bfloat1622float2(h0);
                float2 f1 = __bfloat1622float2(h1);
                __nv_bfloat162 l0 = __float22bfloat162_rn(make_float2(v.x - f0.x, v.y - f0.y));
                __nv_bfloat162 l1 = __float22bfloat162_rn(make_float2(v.z - f1.x, v.w - f1.y));
                uint32_t bo = (uint32_t)(grow * 128 + ghalf * 64 + q * 8);
                uint32_t so = SMEM_SWIZZLE_128B(bo);
                *(uint2 *)(aH + so) = make_uint2(*(uint32_t *)&h0, *(uint32_t *)&h1);
                *(uint2 *)(aL + so) = make_uint2(*(uint32_t *)&l0, *(uint32_t *)&l1);
            }
        }
        // --- copy pre-swizzled B tiles ---
        {
            const uint4 *srcH = (const uint4 *)((const char *)g_WtHi + (size_t)s * 16384);
            const uint4 *srcL = (const uint4 *)((const char *)g_WtLo + (size_t)s * 16384);
            uint4 *dH = (uint4 *)(smc + L3_BHI), *dL = (uint4 *)(smc + L3_BLO);
#pragma unroll
            for (int i = tid; i < 1024; i += 256) {
                dH[i] = __ldg(srcH + i);
                dL[i] = __ldg(srcL + i);
            }
        }
        __syncthreads();
        // --- compute: 4 k-chunks x (3 split terms) ---
#pragma unroll
        for (int kc = 0; kc < 4; kc++) {
            uint32_t kcoff = (uint32_t)kc * 32 + lm_half;
            // A fragments (hi & lo) for 2 m-tiles
            uint32_t Ah[2][4], Al[2][4];
#pragma unroll
            for (int mt = 0; mt < 2; mt++) {
                uint32_t ro = (uint32_t)(warpM * 32 + mt * 16 + lm_row) * 128 + kcoff;
                uint32_t so = SMEM_SWIZZLE_128B(ro);
                ldmx4(Ah[mt][0], Ah[mt][1], Ah[mt][2], Ah[mt][3], sb + L3_AHI + so);
                ldmx4(Al[mt][0], Al[mt][1], Al[mt][2], Al[mt][3], sb + L3_ALO + so);
            }
            // B: 4 n-groups of 16 cols
#pragma unroll
            for (int ng = 0; ng < 4; ng++) {
                uint32_t no = (uint32_t)(warpN * 64 + ng * 16 + lm_row) * 128 + kcoff;
                uint32_t so = SMEM_SWIZZLE_128B(no);
                uint32_t bh0, bh1, bh2, bh3, bl0, bl1, bl2, bl3;
                ldmx4(bh0, bh1, bh2, bh3, sb + L3_BHI + so);
                ldmx4(bl0, bl1, bl2, bl3, sb + L3_BLO + so);
                // n-frag 2*ng: regs {r0, r2}; n-frag 2*ng+1: {r1, r3}
#pragma unroll
                for (int mt = 0; mt < 2; mt++) {
                    mma16816(acc[mt][2 * ng],     Ah[mt], bh0, bh2);
                    mma16816(acc[mt][2 * ng + 1], Ah[mt], bh1, bh3);
                    mma16816(acc[mt][2 * ng],     Ah[mt], bl0, bl2);
                    mma16816(acc[mt][2 * ng + 1], Ah[mt], bl1, bl3);
                    mma16816(acc[mt][2 * ng],     Al[mt], bh0, bh2);
                    mma16816(acc[mt][2 * ng + 1], Al[mt], bh1, bh3);
                }
            }
        }
    }

    // --- epilogue: C + b3 into smem, then (.)@Wf + bf ---
    __syncthreads();
    float *Cs = (float *)smc;   // [128][CSTR] = 67584B, overlaps dead tiles+idx
#pragma unroll
    for (int mt = 0; mt < 2; mt++) {
        int r = warpM * 32 + mt * 16 + (lane >> 2);
#pragma unroll
        for (int nf = 0; nf < 8; nf++) {
            int c = warpN * 64 + nf * 8 + (lane & 3) * 2;
            Cs[r * CSTR + c]           = acc[mt][nf][0] + Wfs[388 + c];
            Cs[r * CSTR + c + 1]       = acc[mt][nf][1] + Wfs[388 + c + 1];
            Cs[(r + 8) * CSTR + c]     = acc[mt][nf][2] + Wfs[388 + c];
            Cs[(r + 8) * CSTR + c + 1] = acc[mt][nf][3] + Wfs[388 + c + 1];
        }
    }
    __syncthreads();
    if (tid < BM) {
        int r = row0 + tid;
        float o0 = Wfs[384], o1 = Wfs[385], o2 = Wfs[386];
        const float *crow = Cs + tid * CSTR;
#pragma unroll 16
        for (int k = 0; k < 128; k++) {
            float v = crow[k];
            o0 = fmaf(v, Wfs[3 * k + 0], o0);
            o1 = fmaf(v, Wfs[3 * k + 1], o1);
            o2 = fmaf(v, Wfs[3 * k + 2], o2);
        }
        if (r < N) {
            float *o = out + ((size_t)b * N + r) * 3;
            o[0] = o0; o[1] = o1; o[2] = o2;
        }
    }
}

// ---------------------------------------------------------------------------
extern "C" void kernel_launch(void *const *d_in, const int *in_sizes, int n_in,
                              void *d_out, int out_size) {
    const float *x   = (const float *)d_in[0];
    const int   *idx = (const int *)d_in[1];
    const float *W0  = (const float *)d_in[2];
    const float *b0  = (const float *)d_in[3];
    const float *W1  = (const float *)d_in[4];
    const float *b1  = (const float *)d_in[5];
    const float *W2  = (const float *)d_in[6];
    const float *b2  = (const float *)d_in[7];
    const float *W3  = (const float *)d_in[8];
    const float *b3  = (const float *)d_in[9];
    const float *Wf  = (const float *)d_in[10];
    const float *bf  = (const float *)d_in[11];
    float *out = (float *)d_out;

    int N = in_sizes[1] / SPI;
    int B = in_sizes[0] / (N * 3);

    float *bufA, *bufB;
    cudaGetSymbolAddress((void **)&bufA, g_bufA);
    cudaGetSymbolAddress((void **)&bufB, g_bufB);

    prep_wt_kernel<<<9, 128>>>(W3);

    dim3 g0((N + 255) / 256, B);
    layer0_kernel<<<g0, 256>>>(x, idx, W0, b0, bufA, N);

    dim3 gl((N + BM - 1) / BM, B);

    size_t sm1 = (size_t)(16 * BM + 16 * 32 + SPI * BM) * 4;
    spiral_layer<16, 32, 2><<<gl, 256, sm1>>>(bufA, idx, W1, b1, bufB, N);

    size_t sm2 = (size_t)(32 * BM + 32 * 64 + SPI * BM) * 4;
    spiral_layer<32, 64, 4><<<gl, 256, sm2>>>(bufB, idx, W2, b2, bufA, N);

    cudaFuncSetAttribute(layer3_mma, cudaFuncAttributeMaxDynamicSharedMemorySize, L3_SMEM);
    layer3_mma<<<gl, 256, L3_SMEM>>>(bufA, idx, b3, Wf, bf, out, N);
}

// round 8
// speedup vs baseline: 2.2171x; 1.2228x over previous
#include <cuda_runtime.h>
#include <cuda_bf16.h>
#include <cstddef>
#include <cstdint>

#define SPI 9
#define BM  128

__device__ float g_bufA[(size_t)8 * 50000 * 64];
__device__ float g_bufB[(size_t)8 * 50000 * 32];
// Pre-transposed, bf16-split, pre-swizzled weights, padded rows of 64 bf16 (128B):
__device__ __nv_bfloat16 g_W1Hi[9 * 32 * 64],  g_W1Lo[9 * 32 * 64];
__device__ __nv_bfloat16 g_W2Hi[9 * 64 * 64],  g_W2Lo[9 * 64 * 64];
__device__ __nv_bfloat16 g_W3Hi[9 * 128 * 64], g_W3Lo[9 * 128 * 64];

__device__ __forceinline__ void ffma2(float2 &d, const float2 &a, const float2 &b) {
    unsigned long long       &du = reinterpret_cast<unsigned long long &>(d);
    const unsigned long long &au = reinterpret_cast<const unsigned long long &>(a);
    const unsigned long long &bu = reinterpret_cast<const unsigned long long &>(b);
    asm("fma.rn.f32x2 %0, %1, %2, %0;" : "+l"(du) : "l"(au), "l"(bu));
}
__device__ __forceinline__ uint32_t smem_u32(const void *p) {
    uint32_t a;
    asm("{ .reg .u64 t; cvta.to.shared.u64 t, %1; cvt.u32.u64 %0, t; }" : "=r"(a) : "l"(p));
    return a;
}
#define SMEM_SWIZZLE_128B(o) ((o) ^ (((o) >> 3) & 0x70))

__device__ __forceinline__ void ldmx4(uint32_t &r0, uint32_t &r1, uint32_t &r2,
                                      uint32_t &r3, uint32_t addr) {
    asm volatile("ldmatrix.sync.aligned.m8n8.x4.shared.b16 {%0,%1,%2,%3}, [%4];"
                 : "=r"(r0), "=r"(r1), "=r"(r2), "=r"(r3) : "r"(addr));
}
__device__ __forceinline__ void mma16816(float *c, const uint32_t *a,
                                         uint32_t b0, uint32_t b1) {
    asm volatile("mma.sync.aligned.m16n8k16.row.col.f32.bf16.bf16.f32 "
                 "{%0,%1,%2,%3}, {%4,%5,%6,%7}, {%8,%9}, {%0,%1,%2,%3};"
                 : "+f"(c[0]), "+f"(c[1]), "+f"(c[2]), "+f"(c[3])
                 : "r"(a[0]), "r"(a[1]), "r"(a[2]), "r"(a[3]), "r"(b0), "r"(b1));
}

// ---------------------------------------------------------------------------
// Layer 0 (FFMA2): Cin=3 -> 16
// ---------------------------------------------------------------------------
__global__ void layer0_kernel(const float *__restrict__ X, const int *__restrict__ idx,
                              const float *__restrict__ W, const float *__restrict__ bias,
                              float *__restrict__ Y, int N) {
    __shared__ float Ws[27 * 16];
    __shared__ float bs[16];
    int tid = threadIdx.x;
    for (int t = tid; t < 27 * 16; t += blockDim.x) Ws[t] = W[t];
    if (tid < 16) bs[tid] = bias[tid];
    __syncthreads();

    int n = blockIdx.x * blockDim.x + tid;
    int b = blockIdx.y;
    if (n >= N) return;

    float2 acc[8];
#pragma unroll
    for (int j = 0; j < 8; j++) acc[j] = make_float2(bs[2 * j], bs[2 * j + 1]);

    const float *Xb = X + (size_t)b * N * 3;
#pragma unroll
    for (int s = 0; s < SPI; s++) {
        int r = idx[n * SPI + s];
        float xv[3];
        xv[0] = __ldg(Xb + (size_t)r * 3 + 0);
        xv[1] = __ldg(Xb + (size_t)r * 3 + 1);
        xv[2] = __ldg(Xb + (size_t)r * 3 + 2);
#pragma unroll
        for (int c = 0; c < 3; c++) {
            const float *wrow = Ws + (s * 3 + c) * 16;
            float2 vv = make_float2(xv[c], xv[c]);
#pragma unroll
            for (int j = 0; j < 8; j++) {
                float2 w = *(const float2 *)(wrow + 2 * j);
                ffma2(acc[j], vv, w);
            }
        }
    }
    float *y = Y + ((size_t)b * N + n) * 16;
#pragma unroll
    for (int j = 0; j < 4; j++)
        *(float4 *)(y + 4 * j) = make_float4(acc[2 * j].x, acc[2 * j].y,
                                             acc[2 * j + 1].x, acc[2 * j + 1].y);
}

// ---------------------------------------------------------------------------
// Weight prep: W[S*CIN, COUT] -> per-s [n=COUT][k padded to 64] bf16 hi/lo, SW128.
// ---------------------------------------------------------------------------
template <int CIN, int COUT>
__global__ void prep_wt(const float *__restrict__ W,
                        __nv_bfloat16 *__restrict__ dstHg,
                        __nv_bfloat16 *__restrict__ dstLg) {
    int s = blockIdx.x;          // 0..8
    int n = threadIdx.x;         // 0..COUT-1
    char *dstH = (char *)dstHg + (size_t)s * COUT * 128;
    char *dstL = (char *)dstLg + (size_t)s * COUT * 128;
    for (int k = 0; k < CIN; k++) {
        float w = __ldg(W + (size_t)(s * CIN + k) * COUT + n);
        __nv_bfloat16 hi = __float2bfloat16_rn(w);
        __nv_bfloat16 lo = __float2bfloat16_rn(w - __bfloat162float(hi));
        uint32_t off = SMEM_SWIZZLE_128B((uint32_t)(n * 128 + k * 2));
        *(__nv_bfloat16 *)(dstH + off) = hi;
        *(__nv_bfloat16 *)(dstL + off) = lo;
    }
}

// ---------------------------------------------------------------------------
// Unified spiral-conv layer via mma.sync bf16x3 split.
// ---------------------------------------------------------------------------
template <int CIN, int COUT, bool FUSE>
__global__ void __launch_bounds__(256, 2)
layer_mma(const float *__restrict__ X,     // [B,N,CIN]
          const int   *__restrict__ idxg,  // [N,9]
          const float *__restrict__ bias,  // [COUT]
          const __nv_bfloat16 *__restrict__ WtH,
          const __nv_bfloat16 *__restrict__ WtL,
          const float *__restrict__ Wf,    // [128,3]  (FUSE)
          const float *__restrict__ bf,    // [3]      (FUSE)
          float *__restrict__ Y,           // [B,N,COUT] or [B,N,3]
          int N) {
    constexpr int KCH = CIN / 16;
    constexpr int WN  = (COUT >= 128) ? 2 : 1;
    constexpr int WM  = 8 / WN;
    constexpr int MT  = 128 / (WM * 16);
    constexpr int NG  = COUT / (WN * 16);
    constexpr int AHI = 0, ALO = 16384, BHI = 32768;
    constexpr int BLO = BHI + COUT * 128;
    constexpr int IDXOFF = BLO + COUT * 128;
    constexpr int PRM = IDXOFF + 4608;
    constexpr int CSTR = 132;

    extern __shared__ __align__(1024) char smc[];
    uint32_t sb = smem_u32(smc);
    int tid = threadIdx.x, wid = tid >> 5, lane = tid & 31;
    int b = blockIdx.y, row0 = blockIdx.x * BM;
    int warpM = wid / WN, warpN = wid % WN;

    int *idxs = (int *)(smc + IDXOFF);
    for (int t = tid; t < SPI * BM; t += 256) {
        int m = t / SPI, s = t % SPI;
        int r = row0 + m;
        if (r >= N) r = N - 1;
        idxs[s * BM + m] = idxg[(size_t)r * SPI + s];
    }
    float *prm = (float *)(smc + PRM);
    if (FUSE) {
        for (int t = tid; t < 384; t += 256) prm[t] = Wf[t];
        if (tid < 3)    prm[384 + tid] = bf[tid];
        if (tid < COUT) prm[388 + tid] = bias[tid];
    } else {
        if (tid < COUT) prm[tid] = bias[tid];
    }

    float acc[MT][2 * NG][4];
#pragma unroll
    for (int mt = 0; mt < MT; mt++)
#pragma unroll
        for (int nf = 0; nf < 2 * NG; nf++)
#pragma unroll
            for (int c = 0; c < 4; c++) acc[mt][nf][c] = 0.0f;

    const float *Xb = X + (size_t)b * N * CIN;
    int grow = tid >> 1, ghalf = tid & 1;
    uint32_t lm_row  = (uint32_t)(lane & 15);
    uint32_t lm_half = (uint32_t)(lane >> 4) << 4;

    __syncthreads();

    for (int s = 0; s < SPI; s++) {
        if (s) __syncthreads();
        // --- gather + bf16 split A tile ---
        {
            int r = idxs[s * BM + grow];
            const float *src = Xb + (size_t)r * CIN + ghalf * (CIN / 2);
            char *aH = smc + AHI, *aL = smc + ALO;
#pragma unroll
            for (int q = 0; q < CIN / 8; q++) {
                float4 v = __ldg((const float4 *)(src + 4 * q));
                __nv_bfloat162 h0 = __float22bfloat162_rn(make_float2(v.x, v.y));
                __nv_bfloat162 h1 = __float22bfloat162_rn(make_float2(v.z, v.w));
                float2 f0 = __bfloat1622float2(h0);
                float2 f1 = __bfloat1622float2(h1);
                __nv_bfloat162 l0 = __float22bfloat162_rn(make_float2(v.x - f0.x, v.y - f0.y));
                __nv_bfloat162 l1 = __float22bfloat162_rn(make_float2(v.z - f1.x, v.w - f1.y));
                uint32_t bo = (uint32_t)(grow * 128 + ghalf * CIN + q * 8);
                uint32_t so = SMEM_SWIZZLE_128B(bo);
                *(uint2 *)(aH + so) = make_uint2(*(uint32_t *)&h0, *(uint32_t *)&h1);
                *(uint2 *)(aL + so) = make_uint2(*(uint32_t *)&l0, *(uint32_t *)&l1);
            }
        }
        // --- copy pre-swizzled B tiles ---
        {
            const uint4 *srcH = (const uint4 *)((const char *)WtH + (size_t)s * COUT * 128);
            const uint4 *srcL = (const uint4 *)((const char *)WtL + (size_t)s * COUT * 128);
            uint4 *dH = (uint4 *)(smc + BHI), *dL = (uint4 *)(smc + BLO);
#pragma unroll
            for (int i = tid; i < COUT * 8; i += 256) {
                dH[i] = __ldg(srcH + i);
                dL[i] = __ldg(srcL + i);
            }
        }
        __syncthreads();
        // --- compute ---
#pragma unroll
        for (int kc = 0; kc < KCH; kc++) {
            uint32_t kcoff = (uint32_t)kc * 32 + lm_half;
            uint32_t Ah[MT][4], Al[MT][4];
#pragma unroll
            for (int mt = 0; mt < MT; mt++) {
                uint32_t ro = (uint32_t)(warpM * (16 * MT) + mt * 16 + lm_row) * 128 + kcoff;
                uint32_t so = SMEM_SWIZZLE_128B(ro);
                ldmx4(Ah[mt][0], Ah[mt][1], Ah[mt][2], Ah[mt][3], sb + AHI + so);
                ldmx4(Al[mt][0], Al[mt][1], Al[mt][2], Al[mt][3], sb + ALO + so);
            }
#pragma unroll
            for (int ng = 0; ng < NG; ng++) {
                uint32_t no = (uint32_t)(warpN * (COUT / WN) + ng * 16 + lm_row) * 128 + kcoff;
                uint32_t so = SMEM_SWIZZLE_128B(no);
                uint32_t bh0, bh1, bh2, bh3, bl0, bl1, bl2, bl3;
                ldmx4(bh0, bh1, bh2, bh3, sb + BHI + so);
                ldmx4(bl0, bl1, bl2, bl3, sb + BLO + so);
#pragma unroll
                for (int mt = 0; mt < MT; mt++) {
                    mma16816(acc[mt][2 * ng],     Ah[mt], bh0, bh2);
                    mma16816(acc[mt][2 * ng + 1], Ah[mt], bh1, bh3);
                    mma16816(acc[mt][2 * ng],     Ah[mt], bl0, bl2);
                    mma16816(acc[mt][2 * ng + 1], Ah[mt], bl1, bl3);
                    mma16816(acc[mt][2 * ng],     Al[mt], bh0, bh2);
                    mma16816(acc[mt][2 * ng + 1], Al[mt], bh1, bh3);
                }
            }
        }
    }

    if (!FUSE) {
        float *Yb = Y + (size_t)b * N * COUT;
#pragma unroll
        for (int mt = 0; mt < MT; mt++) {
            int rr = row0 + warpM * (16 * MT) + mt * 16 + (lane >> 2);
#pragma unroll
            for (int nf = 0; nf < 2 * NG; nf++) {
                int c = warpN * (COUT / WN) + nf * 8 + (lane & 3) * 2;
                float bv0 = prm[c], bv1 = prm[c + 1];
                if (rr < N)
                    *(float2 *)(Yb + (size_t)rr * COUT + c) =
                        make_float2(acc[mt][nf][0] + bv0, acc[mt][nf][1] + bv1);
                if (rr + 8 < N)
                    *(float2 *)(Yb + (size_t)(rr + 8) * COUT + c) =
                        make_float2(acc[mt][nf][2] + bv0, acc[mt][nf][3] + bv1);
            }
        }
    } else {
        __syncthreads();
        float *Cs = (float *)smc;   // [128][CSTR] floats, below PRM region
#pragma unroll
        for (int mt = 0; mt < MT; mt++) {
            int r = warpM * (16 * MT) + mt * 16 + (lane >> 2);
#pragma unroll
            for (int nf = 0; nf < 2 * NG; nf++) {
                int c = warpN * (COUT / WN) + nf * 8 + (lane & 3) * 2;
                Cs[r * CSTR + c]           = acc[mt][nf][0] + prm[388 + c];
                Cs[r * CSTR + c + 1]       = acc[mt][nf][1] + prm[388 + c + 1];
                Cs[(r + 8) * CSTR + c]     = acc[mt][nf][2] + prm[388 + c];
                Cs[(r + 8) * CSTR + c + 1] = acc[mt][nf][3] + prm[388 + c + 1];
            }
        }
        __syncthreads();
        if (tid < BM) {
            int r = row0 + tid;
            float o0 = prm[384], o1 = prm[385], o2 = prm[386];
            const float *crow = Cs + tid * CSTR;
#pragma unroll 16
            for (int k = 0; k < COUT; k++) {
                float v = crow[k];
                o0 = fmaf(v, prm[3 * k + 0], o0);
                o1 = fmaf(v, prm[3 * k + 1], o1);
                o2 = fmaf(v, prm[3 * k + 2], o2);
            }
            if (r < N) {
                float *o = Y + ((size_t)b * N + r) * 3;
                o[0] = o0; o[1] = o1; o[2] = o2;
            }
        }
    }
}

// ---------------------------------------------------------------------------
extern "C" void kernel_launch(void *const *d_in, const int *in_sizes, int n_in,
                              void *d_out, int out_size) {
    const float *x   = (const float *)d_in[0];
    const int   *idx = (const int *)d_in[1];
    const float *W0  = (const float *)d_in[2];
    const float *b0  = (const float *)d_in[3];
    const float *W1  = (const float *)d_in[4];
    const float *b1  = (const float *)d_in[5];
    const float *W2  = (const float *)d_in[6];
    const float *b2  = (const float *)d_in[7];
    const float *W3  = (const float *)d_in[8];
    const float *b3  = (const float *)d_in[9];
    const float *Wf  = (const float *)d_in[10];
    const float *bf  = (const float *)d_in[11];
    float *out = (float *)d_out;

    int N = in_sizes[1] / SPI;
    int B = in_sizes[0] / (N * 3);

    float *bufA, *bufB;
    cudaGetSymbolAddress((void **)&bufA, g_bufA);
    cudaGetSymbolAddress((void **)&bufB, g_bufB);
    __nv_bfloat16 *w1h, *w1l, *w2h, *w2l, *w3h, *w3l;
    cudaGetSymbolAddress((void **)&w1h, g_W1Hi);
    cudaGetSymbolAddress((void **)&w1l, g_W1Lo);
    cudaGetSymbolAddress((void **)&w2h, g_W2Hi);
    cudaGetSymbolAddress((void **)&w2l, g_W2Lo);
    cudaGetSymbolAddress((void **)&w3h, g_W3Hi);
    cudaGetSymbolAddress((void **)&w3l, g_W3Lo);

    constexpr int SM1 = 32768 + 2 * 32 * 128 + 4608 + 32 * 4;
    constexpr int SM2 = 32768 + 2 * 64 * 128 + 4608 + 64 * 4;
    constexpr int SM3 = 32768 + 2 * 128 * 128 + 4608 + (384 + 4 + 128) * 4;
    // REQUIRED: SM2 (54016B) and SM3 (72208B) exceed the 48KB default opt-in.
    cudaFuncSetAttribute(layer_mma<16, 32, false>,
                         cudaFuncAttributeMaxDynamicSharedMemorySize, SM1);
    cudaFuncSetAttribute(layer_mma<32, 64, false>,
                         cudaFuncAttributeMaxDynamicSharedMemorySize, SM2);
    cudaFuncSetAttribute(layer_mma<64, 128, true>,
                         cudaFuncAttributeMaxDynamicSharedMemorySize, SM3);

    prep_wt<16, 32><<<9, 32>>>(W1, w1h, w1l);
    prep_wt<32, 64><<<9, 64>>>(W2, w2h, w2l);
    prep_wt<64, 128><<<9, 128>>>(W3, w3h, w3l);

    dim3 g0((N + 255) / 256, B);
    layer0_kernel<<<g0, 256>>>(x, idx, W0, b0, bufA, N);

    dim3 gl((N + BM - 1) / BM, B);

    layer_mma<16, 32, false><<<gl, 256, SM1>>>(bufA, idx, b1, w1h, w1l,
                                               nullptr, nullptr, bufB, N);
    layer_mma<32, 64, false><<<gl, 256, SM2>>>(bufB, idx, b2, w2h, w2l,
                                               nullptr, nullptr, bufA, N);
    layer_mma<64, 128, true><<<gl, 256, SM3>>>(bufA, idx, b3, w3h, w3l,
                                               Wf, bf, out, N);
}

// round 9
// speedup vs baseline: 2.3917x; 1.0787x over previous
#include <cuda_runtime.h>
#include <cuda_bf16.h>
#include <cstddef>
#include <cstdint>

#define SPI 9
#define BM  128

// Activations stored pre-split: per vertex [hi bf16 x C | lo bf16 x C].
__device__ __align__(16) __nv_bfloat16 g_bufX[(size_t)8 * 50000 * 128]; // L0 out (64B/row) / L2 out (256B/row)
__device__ __align__(16) __nv_bfloat16 g_bufY[(size_t)8 * 50000 * 64];  // L1 out (128B/row)
// Pre-transposed, bf16-split, pre-swizzled weights ([n][k padded to 64] rows):
__device__ __align__(16) __nv_bfloat16 g_W1Hi[9 * 32 * 64],  g_W1Lo[9 * 32 * 64];
__device__ __align__(16) __nv_bfloat16 g_W2Hi[9 * 64 * 64],  g_W2Lo[9 * 64 * 64];
__device__ __align__(16) __nv_bfloat16 g_W3Hi[9 * 128 * 64], g_W3Lo[9 * 128 * 64];

__device__ __forceinline__ void ffma2(float2 &d, const float2 &a, const float2 &b) {
    unsigned long long       &du = reinterpret_cast<unsigned long long &>(d);
    const unsigned long long &au = reinterpret_cast<const unsigned long long &>(a);
    const unsigned long long &bu = reinterpret_cast<const unsigned long long &>(b);
    asm("fma.rn.f32x2 %0, %1, %2, %0;" : "+l"(du) : "l"(au), "l"(bu));
}
__device__ __forceinline__ uint32_t smem_u32(const void *p) {
    uint32_t a;
    asm("{ .reg .u64 t; cvta.to.shared.u64 t, %1; cvt.u32.u64 %0, t; }" : "=r"(a) : "l"(p));
    return a;
}
#define SMEM_SWIZZLE_128B(o) ((o) ^ (((o) >> 3) & 0x70))

__device__ __forceinline__ void cp16(uint32_t dst, const void *src) {
    asm volatile("cp.async.cg.shared.global [%0], [%1], 16;" :: "r"(dst), "l"(src));
}
#define CP_COMMIT() asm volatile("cp.async.commit_group;" ::: "memory")
#define CP_WAIT0()  asm volatile("cp.async.wait_group 0;" ::: "memory")

__device__ __forceinline__ void ldmx4(uint32_t &r0, uint32_t &r1, uint32_t &r2,
                                      uint32_t &r3, uint32_t addr) {
    asm volatile("ldmatrix.sync.aligned.m8n8.x4.shared.b16 {%0,%1,%2,%3}, [%4];"
                 : "=r"(r0), "=r"(r1), "=r"(r2), "=r"(r3) : "r"(addr));
}
__device__ __forceinline__ void mma16816(float *c, const uint32_t *a,
                                         uint32_t b0, uint32_t b1) {
    asm volatile("mma.sync.aligned.m16n8k16.row.col.f32.bf16.bf16.f32 "
                 "{%0,%1,%2,%3}, {%4,%5,%6,%7}, {%8,%9}, {%0,%1,%2,%3};"
                 : "+f"(c[0]), "+f"(c[1]), "+f"(c[2]), "+f"(c[3])
                 : "r"(a[0]), "r"(a[1]), "r"(a[2]), "r"(a[3]), "r"(b0), "r"(b1));
}
// split v into hi/lo bf16x2 packed words
__device__ __forceinline__ void split2(float2 v, uint32_t &h, uint32_t &l) {
    __nv_bfloat162 hb = __float22bfloat162_rn(v);
    float2 hf = __bfloat1622float2(hb);
    __nv_bfloat162 lb = __float22bfloat162_rn(make_float2(v.x - hf.x, v.y - hf.y));
    h = *(uint32_t *)&hb;
    l = *(uint32_t *)&lb;
}

// ---------------------------------------------------------------------------
// Layer 0 (FFMA2): Cin=3 -> 16, writes pre-split hi/lo rows (64B/vertex).
// ---------------------------------------------------------------------------
__global__ void layer0_kernel(const float *__restrict__ X, const int *__restrict__ idx,
                              const float *__restrict__ W, const float *__restrict__ bias,
                              __nv_bfloat16 *__restrict__ Y, int N) {
    __shared__ float Ws[27 * 16];
    __shared__ float bs[16];
    int tid = threadIdx.x;
    for (int t = tid; t < 27 * 16; t += blockDim.x) Ws[t] = W[t];
    if (tid < 16) bs[tid] = bias[tid];
    __syncthreads();

    int n = blockIdx.x * blockDim.x + tid;
    int b = blockIdx.y;
    if (n >= N) return;

    float2 acc[8];
#pragma unroll
    for (int j = 0; j < 8; j++) acc[j] = make_float2(bs[2 * j], bs[2 * j + 1]);

    const float *Xb = X + (size_t)b * N * 3;
#pragma unroll
    for (int s = 0; s < SPI; s++) {
        int r = idx[n * SPI + s];
        float xv[3];
        xv[0] = __ldg(Xb + (size_t)r * 3 + 0);
        xv[1] = __ldg(Xb + (size_t)r * 3 + 1);
        xv[2] = __ldg(Xb + (size_t)r * 3 + 2);
#pragma unroll
        for (int c = 0; c < 3; c++) {
            const float *wrow = Ws + (s * 3 + c) * 16;
            float2 vv = make_float2(xv[c], xv[c]);
#pragma unroll
            for (int j = 0; j < 8; j++) {
                float2 w = *(const float2 *)(wrow + 2 * j);
                ffma2(acc[j], vv, w);
            }
        }
    }
    uint32_t hi[8], lo[8];
#pragma unroll
    for (int j = 0; j < 8; j++) split2(acc[j], hi[j], lo[j]);
    char *y = (char *)Y + ((size_t)b * N + n) * 64;
    *(uint4 *)(y + 0)  = make_uint4(hi[0], hi[1], hi[2], hi[3]);
    *(uint4 *)(y + 16) = make_uint4(hi[4], hi[5], hi[6], hi[7]);
    *(uint4 *)(y + 32) = make_uint4(lo[0], lo[1], lo[2], lo[3]);
    *(uint4 *)(y + 48) = make_uint4(lo[4], lo[5], lo[6], lo[7]);
}

// ---------------------------------------------------------------------------
// Weight prep: W[S*CIN, COUT] -> per-s [n=COUT][k pad 64] bf16 hi/lo, SW128.
// ---------------------------------------------------------------------------
template <int CIN, int COUT>
__global__ void prep_wt(const float *__restrict__ W,
                        __nv_bfloat16 *__restrict__ dstHg,
                        __nv_bfloat16 *__restrict__ dstLg) {
    int s = blockIdx.x;
    int n = threadIdx.x;
    char *dstH = (char *)dstHg + (size_t)s * COUT * 128;
    char *dstL = (char *)dstLg + (size_t)s * COUT * 128;
    for (int k = 0; k < CIN; k++) {
        float w = __ldg(W + (size_t)(s * CIN + k) * COUT + n);
        __nv_bfloat16 hi = __float2bfloat16_rn(w);
        __nv_bfloat16 lo = __float2bfloat16_rn(w - __bfloat162float(hi));
        uint32_t off = SMEM_SWIZZLE_128B((uint32_t)(n * 128 + k * 2));
        *(__nv_bfloat16 *)(dstH + off) = hi;
        *(__nv_bfloat16 *)(dstL + off) = lo;
    }
}

// ---------------------------------------------------------------------------
// Unified spiral-conv layer: bf16x3 mma.sync + cp.async 2-stage pipeline.
// X rows are pre-split: [hi bf16 x CIN | lo bf16 x CIN] (4*CIN bytes).
// ---------------------------------------------------------------------------
template <int CIN, int COUT, bool FUSE>
__global__ void __launch_bounds__(256, FUSE ? 1 : 2)
layer_mma(const __nv_bfloat16 *__restrict__ X,
          const int   *__restrict__ idxg,
          const float *__restrict__ bias,
          const __nv_bfloat16 *__restrict__ WtH,
          const __nv_bfloat16 *__restrict__ WtL,
          const float *__restrict__ Wf,
          const float *__restrict__ bf,
          void *__restrict__ Y,             // bf16 split rows, or float[B,N,3] if FUSE
          int N) {
    constexpr int KCH = CIN / 16;
    constexpr int WN  = (COUT >= 128) ? 2 : 1;
    constexpr int WM  = 8 / WN;
    constexpr int MT  = 128 / (WM * 16);
    constexpr int NG  = COUT / (WN * 16);
    constexpr int CB  = 2 * CIN;          // bytes per hi row of A source
    constexpr int CPT = CB / 32;          // chunks per thread per tile (2 thr/row)
    constexpr int XROW = 4 * CIN;         // full source row stride in bytes
    constexpr int BSZ = COUT * 128;       // one B tile (hi or lo)
    constexpr int BB  = 65536;            // B region base (A region = 4x16KB)
    constexpr int IDXOFF = BB + 4 * BSZ;
    constexpr int PRM = IDXOFF + 4608;
    constexpr int CSTR = 132;

    extern __shared__ __align__(1024) char smc[];
    uint32_t sb = smem_u32(smc);
    int tid = threadIdx.x, wid = tid >> 5, lane = tid & 31;
    int b = blockIdx.y, row0 = blockIdx.x * BM;
    int warpM = wid / WN, warpN = wid % WN;

    int *idxs = (int *)(smc + IDXOFF);
    for (int t = tid; t < SPI * BM; t += 256) {
        int m = t / SPI, s = t % SPI;
        int r = row0 + m;
        if (r >= N) r = N - 1;
        idxs[s * BM + m] = idxg[(size_t)r * SPI + s];
    }
    float *prm = (float *)(smc + PRM);
    if (FUSE) {
        for (int t = tid; t < 384; t += 256) prm[t] = Wf[t];
        if (tid < 3)    prm[384 + tid] = bf[tid];
        if (tid < COUT) prm[388 + tid] = bias[tid];
    } else {
        if (tid < COUT) prm[tid] = bias[tid];
    }

    float acc[MT][2 * NG][4];
#pragma unroll
    for (int mt = 0; mt < MT; mt++)
#pragma unroll
        for (int nf = 0; nf < 2 * NG; nf++)
#pragma unroll
            for (int c = 0; c < 4; c++) acc[mt][nf][c] = 0.0f;

    const char *Xb = (const char *)X + (size_t)b * N * XROW;
    int grow = tid >> 1, ghalf = tid & 1;
    uint32_t lm_row  = (uint32_t)(lane & 15);
    uint32_t lm_half = (uint32_t)(lane >> 4) << 4;

    __syncthreads();   // idxs ready before any gather issue

    auto issueA = [&](int s, int st) {
        int r = idxs[s * BM + grow];
        const char *src = Xb + (size_t)r * XROW;
        uint32_t ah = sb + (uint32_t)st * 16384;
        uint32_t al = sb + 32768 + (uint32_t)st * 16384;
#pragma unroll
        for (int q = 0; q < CPT; q++) {
            int c = ghalf * CPT + q;
            uint32_t so = SMEM_SWIZZLE_128B((uint32_t)(grow * 128 + 16 * c));
            cp16(ah + so, src + 16 * c);
            cp16(al + so, src + CB + 16 * c);
        }
    };
    auto issueB = [&](int s, int st) {
        const char *sH = (const char *)WtH + (size_t)s * BSZ;
        const char *sL = (const char *)WtL + (size_t)s * BSZ;
        uint32_t bh = sb + BB + (uint32_t)st * 2 * BSZ;
        uint32_t bl = bh + BSZ;
#pragma unroll
        for (int i = tid * 16; i < BSZ; i += 256 * 16) {
            cp16(bh + i, sH + i);
            cp16(bl + i, sL + i);
        }
    };

    issueA(0, 0);
    issueB(0, 0);
    CP_COMMIT();

    for (int s = 0; s < SPI; s++) {
        int st = s & 1;
        CP_WAIT0();
        __syncthreads();
        if (s + 1 < SPI) {
            issueA(s + 1, st ^ 1);
            issueB(s + 1, st ^ 1);
            CP_COMMIT();
        }
        // --- compute step s from stage st ---
        uint32_t aH = sb + (uint32_t)st * 16384;
        uint32_t aL = sb + 32768 + (uint32_t)st * 16384;
        uint32_t bH = sb + BB + (uint32_t)st * 2 * BSZ;
        uint32_t bL = bH + BSZ;
#pragma unroll
        for (int kc = 0; kc < KCH; kc++) {
            uint32_t kcoff = (uint32_t)kc * 32 + lm_half;
            uint32_t Ah[MT][4], Al[MT][4];
#pragma unroll
            for (int mt = 0; mt < MT; mt++) {
                uint32_t ro = (uint32_t)(warpM * (16 * MT) + mt * 16 + lm_row) * 128 + kcoff;
                uint32_t so = SMEM_SWIZZLE_128B(ro);
                ldmx4(Ah[mt][0], Ah[mt][1], Ah[mt][2], Ah[mt][3], aH + so);
                ldmx4(Al[mt][0], Al[mt][1], Al[mt][2], Al[mt][3], aL + so);
            }
#pragma unroll
            for (int ng = 0; ng < NG; ng++) {
                uint32_t no = (uint32_t)(warpN * (COUT / WN) + ng * 16 + lm_row) * 128 + kcoff;
                uint32_t so = SMEM_SWIZZLE_128B(no);
                uint32_t bh0, bh1, bh2, bh3, bl0, bl1, bl2, bl3;
                ldmx4(bh0, bh1, bh2, bh3, bH + so);
                ldmx4(bl0, bl1, bl2, bl3, bL + so);
#pragma unroll
                for (int mt = 0; mt < MT; mt++) {
                    mma16816(acc[mt][2 * ng],     Ah[mt], bh0, bh2);
                    mma16816(acc[mt][2 * ng + 1], Ah[mt], bh1, bh3);
                    mma16816(acc[mt][2 * ng],     Ah[mt], bl0, bl2);
                    mma16816(acc[mt][2 * ng + 1], Ah[mt], bl1, bl3);
                    mma16816(acc[mt][2 * ng],     Al[mt], bh0, bh2);
                    mma16816(acc[mt][2 * ng + 1], Al[mt], bh1, bh3);
                }
            }
        }
    }

    if (!FUSE) {
        // write pre-split hi/lo rows (+bias)
        char *Yb = (char *)Y + (size_t)b * N * (4 * COUT);
#pragma unroll
        for (int mt = 0; mt < MT; mt++) {
            int rr = row0 + warpM * (16 * MT) + mt * 16 + (lane >> 2);
#pragma unroll
            for (int nf = 0; nf < 2 * NG; nf++) {
                int c = warpN * (COUT / WN) + nf * 8 + (lane & 3) * 2;
                float bv0 = prm[c], bv1 = prm[c + 1];
                uint32_t h, l;
                if (rr < N) {
                    split2(make_float2(acc[mt][nf][0] + bv0, acc[mt][nf][1] + bv1), h, l);
                    char *rp = Yb + (size_t)rr * (4 * COUT);
                    *(uint32_t *)(rp + 2 * c) = h;
                    *(uint32_t *)(rp + 2 * COUT + 2 * c) = l;
                }
                if (rr + 8 < N) {
                    split2(make_float2(acc[mt][nf][2] + bv0, acc[mt][nf][3] + bv1), h, l);
                    char *rp = Yb + (size_t)(rr + 8) * (4 * COUT);
                    *(uint32_t *)(rp + 2 * c) = h;
                    *(uint32_t *)(rp + 2 * COUT + 2 * c) = l;
                }
            }
        }
    } else {
        __syncthreads();
        float *Cs = (float *)smc;   // [128][CSTR] floats = 67584B < IDXOFF
#pragma unroll
        for (int mt = 0; mt < MT; mt++) {
            int r = warpM * (16 * MT) + mt * 16 + (lane >> 2);
#pragma unroll
            for (int nf = 0; nf < 2 * NG; nf++) {
                int c = warpN * (COUT / WN) + nf * 8 + (lane & 3) * 2;
                Cs[r * CSTR + c]           = acc[mt][nf][0] + prm[388 + c];
                Cs[r * CSTR + c + 1]       = acc[mt][nf][1] + prm[388 + c + 1];
                Cs[(r + 8) * CSTR + c]     = acc[mt][nf][2] + prm[388 + c];
                Cs[(r + 8) * CSTR + c + 1] = acc[mt][nf][3] + prm[388 + c + 1];
            }
        }
        __syncthreads();
        if (tid < BM) {
            int r = row0 + tid;
            float o0 = prm[384], o1 = prm[385], o2 = prm[386];
            const float *crow = Cs + tid * CSTR;
#pragma unroll 16
            for (int k = 0; k < COUT; k++) {
                float v = crow[k];
                o0 = fmaf(v, prm[3 * k + 0], o0);
                o1 = fmaf(v, prm[3 * k + 1], o1);
                o2 = fmaf(v, prm[3 * k + 2], o2);
            }
            if (r < N) {
                float *o = (float *)Y + ((size_t)b * N + r) * 3;
                o[0] = o0; o[1] = o1; o[2] = o2;
            }
        }
    }
}

// ---------------------------------------------------------------------------
extern "C" void kernel_launch(void *const *d_in, const int *in_sizes, int n_in,
                              void *d_out, int out_size) {
    const float *x   = (const float *)d_in[0];
    const int   *idx = (const int *)d_in[1];
    const float *W0  = (const float *)d_in[2];
    const float *b0  = (const float *)d_in[3];
    const float *W1  = (const float *)d_in[4];
    const float *b1  = (const float *)d_in[5];
    const float *W2  = (const float *)d_in[6];
    const float *b2  = (const float *)d_in[7];
    const float *W3  = (const float *)d_in[8];
    const float *b3  = (const float *)d_in[9];
    const float *Wf  = (const float *)d_in[10];
    const float *bf  = (const float *)d_in[11];
    float *out = (float *)d_out;

    int N = in_sizes[1] / SPI;
    int B = in_sizes[0] / (N * 3);

    __nv_bfloat16 *bufX, *bufY;
    cudaGetSymbolAddress((void **)&bufX, g_bufX);
    cudaGetSymbolAddress((void **)&bufY, g_bufY);
    __nv_bfloat16 *w1h, *w1l, *w2h, *w2l, *w3h, *w3l;
    cudaGetSymbolAddress((void **)&w1h, g_W1Hi);
    cudaGetSymbolAddress((void **)&w1l, g_W1Lo);
    cudaGetSymbolAddress((void **)&w2h, g_W2Hi);
    cudaGetSymbolAddress((void **)&w2l, g_W2Lo);
    cudaGetSymbolAddress((void **)&w3h, g_W3Hi);
    cudaGetSymbolAddress((void **)&w3l, g_W3Lo);

    constexpr int SM1 = 65536 + 4 * (32 * 128)  + 4608 + 32 * 4;
    constexpr int SM2 = 65536 + 4 * (64 * 128)  + 4608 + 64 * 4;
    constexpr int SM3 = 65536 + 4 * (128 * 128) + 4608 + (384 + 4 + 128) * 4;
    cudaFuncSetAttribute(layer_mma<16, 32, false>,
                         cudaFuncAttributeMaxDynamicSharedMemorySize, SM1);
    cudaFuncSetAttribute(layer_mma<32, 64, false>,
                         cudaFuncAttributeMaxDynamicSharedMemorySize, SM2);
    cudaFuncSetAttribute(layer_mma<64, 128, true>,
                         cudaFuncAttributeMaxDynamicSharedMemorySize, SM3);

    prep_wt<16, 32><<<9, 32>>>(W1, w1h, w1l);
    prep_wt<32, 64><<<9, 64>>>(W2, w2h, w2l);
    prep_wt<64, 128><<<9, 128>>>(W3, w3h, w3l);

    dim3 g0((N + 255) / 256, B);
    layer0_kernel<<<g0, 256>>>(x, idx, W0, b0, bufX, N);   // 64B rows

    dim3 gl((N + BM - 1) / BM, B);
    layer_mma<16, 32, false><<<gl, 256, SM1>>>(bufX, idx, b1, w1h, w1l,
                                               nullptr, nullptr, bufY, N);  // 128B rows
    layer_mma<32, 64, false><<<gl, 256, SM2>>>(bufY, idx, b2, w2h, w2l,
                                               nullptr, nullptr, bufX, N);  // 256B rows
    layer_mma<64, 128, true><<<gl, 256, SM3>>>(bufX, idx, b3, w3h, w3l,
                                               Wf, bf, out, N);
}

// round 10
// speedup vs baseline: 2.7509x; 1.1502x over previous
#include <cuda_runtime.h>
#include <cuda_bf16.h>
#include <cstddef>
#include <cstdint>

#define SPI 9
#define BM  128

// Activations stored pre-split: per vertex [hi bf16 x C | lo bf16 x C].
__device__ __align__(16) __nv_bfloat16 g_bufX[(size_t)8 * 50000 * 128]; // L0 out (64B/row) / L2 out (256B/row)
__device__ __align__(16) __nv_bfloat16 g_bufY[(size_t)8 * 50000 * 64];  // L1 out (128B/row)
// Weights pre-shuffled into mma.sync B-fragment order:
//   WF[s][kc][ngg][h][lane] : uint4 = {b_n0_klo, b_n8_klo, b_n0_khi, b_n8_khi}
__device__ __align__(16) uint4 g_WF1[9 * 1 * 2 * 2 * 32];
__device__ __align__(16) uint4 g_WF2[9 * 2 * 4 * 2 * 32];
__device__ __align__(16) uint4 g_WF3[9 * 4 * 8 * 2 * 32];

__device__ __forceinline__ void ffma2(float2 &d, const float2 &a, const float2 &b) {
    unsigned long long       &du = reinterpret_cast<unsigned long long &>(d);
    const unsigned long long &au = reinterpret_cast<const unsigned long long &>(a);
    const unsigned long long &bu = reinterpret_cast<const unsigned long long &>(b);
    asm("fma.rn.f32x2 %0, %1, %2, %0;" : "+l"(du) : "l"(au), "l"(bu));
}
__device__ __forceinline__ uint32_t smem_u32(const void *p) {
    uint32_t a;
    asm("{ .reg .u64 t; cvta.to.shared.u64 t, %1; cvt.u32.u64 %0, t; }" : "=r"(a) : "l"(p));
    return a;
}
#define SMEM_SWIZZLE_128B(o) ((o) ^ (((o) >> 3) & 0x70))

__device__ __forceinline__ void cp16(uint32_t dst, const void *src) {
    asm volatile("cp.async.cg.shared.global [%0], [%1], 16;" :: "r"(dst), "l"(src));
}
#define CP_COMMIT() asm volatile("cp.async.commit_group;" ::: "memory")
#define CP_WAIT0()  asm volatile("cp.async.wait_group 0;" ::: "memory")

__device__ __forceinline__ void ldmx4(uint32_t &r0, uint32_t &r1, uint32_t &r2,
                                      uint32_t &r3, uint32_t addr) {
    asm volatile("ldmatrix.sync.aligned.m8n8.x4.shared.b16 {%0,%1,%2,%3}, [%4];"
                 : "=r"(r0), "=r"(r1), "=r"(r2), "=r"(r3) : "r"(addr));
}
__device__ __forceinline__ void mma16816(float *c, const uint32_t *a,
                                         uint32_t b0, uint32_t b1) {
    asm volatile("mma.sync.aligned.m16n8k16.row.col.f32.bf16.bf16.f32 "
                 "{%0,%1,%2,%3}, {%4,%5,%6,%7}, {%8,%9}, {%0,%1,%2,%3};"
                 : "+f"(c[0]), "+f"(c[1]), "+f"(c[2]), "+f"(c[3])
                 : "r"(a[0]), "r"(a[1]), "r"(a[2]), "r"(a[3]), "r"(b0), "r"(b1));
}
__device__ __forceinline__ void split2(float2 v, uint32_t &h, uint32_t &l) {
    __nv_bfloat162 hb = __float22bfloat162_rn(v);
    float2 hf = __bfloat1622float2(hb);
    __nv_bfloat162 lb = __float22bfloat162_rn(make_float2(v.x - hf.x, v.y - hf.y));
    h = *(uint32_t *)&hb;
    l = *(uint32_t *)&lb;
}

// ---------------------------------------------------------------------------
// Layer 0 (FFMA2): Cin=3 -> 16, writes pre-split hi/lo rows (64B/vertex).
// ---------------------------------------------------------------------------
__global__ void layer0_kernel(const float *__restrict__ X, const int *__restrict__ idx,
                              const float *__restrict__ W, const float *__restrict__ bias,
                              __nv_bfloat16 *__restrict__ Y, int N) {
    __shared__ float Ws[27 * 16];
    __shared__ float bs[16];
    int tid = threadIdx.x;
    for (int t = tid; t < 27 * 16; t += blockDim.x) Ws[t] = W[t];
    if (tid < 16) bs[tid] = bias[tid];
    __syncthreads();

    int n = blockIdx.x * blockDim.x + tid;
    int b = blockIdx.y;
    if (n >= N) return;

    float2 acc[8];
#pragma unroll
    for (int j = 0; j < 8; j++) acc[j] = make_float2(bs[2 * j], bs[2 * j + 1]);

    const float *Xb = X + (size_t)b * N * 3;
#pragma unroll
    for (int s = 0; s < SPI; s++) {
        int r = idx[n * SPI + s];
        float xv[3];
        xv[0] = __ldg(Xb + (size_t)r * 3 + 0);
        xv[1] = __ldg(Xb + (size_t)r * 3 + 1);
        xv[2] = __ldg(Xb + (size_t)r * 3 + 2);
#pragma unroll
        for (int c = 0; c < 3; c++) {
            const float *wrow = Ws + (s * 3 + c) * 16;
            float2 vv = make_float2(xv[c], xv[c]);
#pragma unroll
            for (int j = 0; j < 8; j++) {
                float2 w = *(const float2 *)(wrow + 2 * j);
                ffma2(acc[j], vv, w);
            }
        }
    }
    uint32_t hi[8], lo[8];
#pragma unroll
    for (int j = 0; j < 8; j++) split2(acc[j], hi[j], lo[j]);
    char *y = (char *)Y + ((size_t)b * N + n) * 64;
    *(uint4 *)(y + 0)  = make_uint4(hi[0], hi[1], hi[2], hi[3]);
    *(uint4 *)(y + 16) = make_uint4(hi[4], hi[5], hi[6], hi[7]);
    *(uint4 *)(y + 32) = make_uint4(lo[0], lo[1], lo[2], lo[3]);
    *(uint4 *)(y + 48) = make_uint4(lo[4], lo[5], lo[6], lo[7]);
}

// ---------------------------------------------------------------------------
// Weight prep: W[S*CIN, COUT] -> mma B-fragment order, bf16 hi/lo.
// entry i within s: lane=i&31, h=(i>>5)&1, ngg=(i>>6)%NGT, kc=(i>>6)/NGT
// ---------------------------------------------------------------------------
template <int CIN, int COUT>
__global__ void prep_wfrag(const float *__restrict__ W, uint4 *__restrict__ dst) {
    constexpr int KCH = CIN / 16, NGT = COUT / 16;
    constexpr int PER = KCH * NGT * 64;
    int s = blockIdx.x;
    for (int i = threadIdx.x; i < PER; i += blockDim.x) {
        int lane = i & 31, h = (i >> 5) & 1, ngg = (i >> 6) % NGT, kc = (i >> 6) / NGT;
        int n0 = ngg * 16 + (lane >> 2);
        int kb = kc * 16 + 2 * (lane & 3);
        auto wsel = [&](int k, int n) -> uint32_t {
            float v = __ldg(W + (size_t)(s * CIN + k) * COUT + n);
            __nv_bfloat16 hb = __float2bfloat16_rn(v);
            if (h == 0) return (uint32_t)(*(uint16_t *)&hb);
            float r = v - __bfloat162float(hb);
            __nv_bfloat16 lb = __float2bfloat16_rn(r);
            return (uint32_t)(*(uint16_t *)&lb);
        };
        auto word = [&](int k, int n) { return wsel(k, n) | (wsel(k + 1, n) << 16); };
        uint4 q;
        q.x = word(kb,     n0);       // n-lo, k-lo
        q.y = word(kb,     n0 + 8);   // n-hi, k-lo
        q.z = word(kb + 8, n0);       // n-lo, k-hi
        q.w = word(kb + 8, n0 + 8);   // n-hi, k-hi
        dst[(size_t)s * PER + i] = q;
    }
}

// ---------------------------------------------------------------------------
// Unified spiral-conv layer: bf16x3 mma.sync; A via cp.async double-buffered
// smem gather; B via direct per-lane LDG.128 of pre-shuffled fragments.
// ---------------------------------------------------------------------------
template <int CIN, int COUT, bool FUSE>
__global__ void __launch_bounds__(256, 2)
layer_mma(const __nv_bfloat16 *__restrict__ X,
          const int   *__restrict__ idxg,
          const float *__restrict__ bias,
          const uint4 *__restrict__ WF,
          const float *__restrict__ Wf,
          const float *__restrict__ bf,
          void *__restrict__ Y,
          int N) {
    constexpr int KCH = CIN / 16;
    constexpr int NGT = COUT / 16;
    constexpr int WN  = (COUT >= 128) ? 2 : 1;
    constexpr int WM  = 8 / WN;
    constexpr int MT  = 128 / (WM * 16);
    constexpr int NG  = NGT / WN;
    constexpr int CB  = 2 * CIN;
    constexpr int CPT = CB / 32;
    constexpr int XROW = 4 * CIN;
    constexpr int IDXOFF = 65536;          // A region: hi st0/st1, lo st0/st1 (4x16KB)
    constexpr int PRM = IDXOFF + 4608;
    constexpr int CSTR = 132;

    extern __shared__ __align__(1024) char smc[];
    uint32_t sb = smem_u32(smc);
    int tid = threadIdx.x, wid = tid >> 5, lane = tid & 31;
    int b = blockIdx.y, row0 = blockIdx.x * BM;
    int warpM = wid / WN, warpN = wid % WN;

    int *idxs = (int *)(smc + IDXOFF);
    for (int t = tid; t < SPI * BM; t += 256) {
        int m = t / SPI, s = t % SPI;
        int r = row0 + m;
        if (r >= N) r = N - 1;
        idxs[s * BM + m] = idxg[(size_t)r * SPI + s];
    }
    float *prm = (float *)(smc + PRM);
    if (FUSE) {
        for (int t = tid; t < 384; t += 256) prm[t] = Wf[t];
        if (tid < 3)    prm[384 + tid] = bf[tid];
        if (tid < COUT) prm[388 + tid] = bias[tid];
    } else {
        if (tid < COUT) prm[tid] = bias[tid];
    }

    float acc[MT][2 * NG][4];
#pragma unroll
    for (int mt = 0; mt < MT; mt++)
#pragma unroll
        for (int nf = 0; nf < 2 * NG; nf++)
#pragma unroll
            for (int c = 0; c < 4; c++) acc[mt][nf][c] = 0.0f;

    const char *Xb = (const char *)X + (size_t)b * N * XROW;
    int grow = tid >> 1, ghalf = tid & 1;
    uint32_t lm_row  = (uint32_t)(lane & 15);
    uint32_t lm_half = (uint32_t)(lane >> 4) << 4;

    __syncthreads();   // idxs ready

    auto issueA = [&](int s, int st) {
        int r = idxs[s * BM + grow];
        const char *src = Xb + (size_t)r * XROW;
        uint32_t ah = sb + (uint32_t)st * 16384;
        uint32_t al = sb + 32768 + (uint32_t)st * 16384;
#pragma unroll
        for (int q = 0; q < CPT; q++) {
            int c = ghalf * CPT + q;
            uint32_t so = SMEM_SWIZZLE_128B((uint32_t)(grow * 128 + 16 * c));
            cp16(ah + so, src + 16 * c);
            cp16(al + so, src + CB + 16 * c);
        }
    };

    issueA(0, 0);
    CP_COMMIT();

    for (int s = 0; s < SPI; s++) {
        int st = s & 1;
        CP_WAIT0();
        __syncthreads();
        if (s + 1 < SPI) {
            issueA(s + 1, st ^ 1);
            CP_COMMIT();
        }
        uint32_t aH = sb + (uint32_t)st * 16384;
        uint32_t aL = sb + 32768 + (uint32_t)st * 16384;
#pragma unroll
        for (int kc = 0; kc < KCH; kc++) {
            uint32_t kcoff = (uint32_t)kc * 32 + lm_half;
            uint32_t Ah[MT][4], Al[MT][4];
#pragma unroll
            for (int mt = 0; mt < MT; mt++) {
                uint32_t ro = (uint32_t)(warpM * (16 * MT) + mt * 16 + lm_row) * 128 + kcoff;
                uint32_t so = SMEM_SWIZZLE_128B(ro);
                ldmx4(Ah[mt][0], Ah[mt][1], Ah[mt][2], Ah[mt][3], aH + so);
                ldmx4(Al[mt][0], Al[mt][1], Al[mt][2], Al[mt][3], aL + so);
            }
#pragma unroll
            for (int ng = 0; ng < NG; ng++) {
                int ngg = warpN * NG + ng;
                const uint4 *bp = WF + ((((size_t)s * KCH + kc) * NGT + ngg) * 2) * 32 + lane;
                uint4 qh = __ldg(bp);
                uint4 ql = __ldg(bp + 32);
#pragma unroll
                for (int mt = 0; mt < MT; mt++) {
                    mma16816(acc[mt][2 * ng],     Ah[mt], qh.x, qh.z);
                    mma16816(acc[mt][2 * ng + 1], Ah[mt], qh.y, qh.w);
                    mma16816(acc[mt][2 * ng],     Ah[mt], ql.x, ql.z);
                    mma16816(acc[mt][2 * ng + 1], Ah[mt], ql.y, ql.w);
                    mma16816(acc[mt][2 * ng],     Al[mt], qh.x, qh.z);
                    mma16816(acc[mt][2 * ng + 1], Al[mt], qh.y, qh.w);
                }
            }
        }
    }

    if (!FUSE) {
        char *Yb = (char *)Y + (size_t)b * N * (4 * COUT);
#pragma unroll
        for (int mt = 0; mt < MT; mt++) {
            int rr = row0 + warpM * (16 * MT) + mt * 16 + (lane >> 2);
#pragma unroll
            for (int nf = 0; nf < 2 * NG; nf++) {
                int c = warpN * (COUT / WN) + nf * 8 + (lane & 3) * 2;
                float bv0 = prm[c], bv1 = prm[c + 1];
                uint32_t h, l;
                if (rr < N) {
                    split2(make_float2(acc[mt][nf][0] + bv0, acc[mt][nf][1] + bv1), h, l);
                    char *rp = Yb + (size_t)rr * (4 * COUT);
                    *(uint32_t *)(rp + 2 * c) = h;
                    *(uint32_t *)(rp + 2 * COUT + 2 * c) = l;
                }
                if (rr + 8 < N) {
                    split2(make_float2(acc[mt][nf][2] + bv0, acc[mt][nf][3] + bv1), h, l);
                    char *rp = Yb + (size_t)(rr + 8) * (4 * COUT);
                    *(uint32_t *)(rp + 2 * c) = h;
                    *(uint32_t *)(rp + 2 * COUT + 2 * c) = l;
                }
            }
        }
    } else {
        __syncthreads();
        float *Cs = (float *)smc;   // [128][CSTR] = 67584B; overlaps dead A+idx, not prm
#pragma unroll
        for (int mt = 0; mt < MT; mt++) {
            int r = warpM * (16 * MT) + mt * 16 + (lane >> 2);
#pragma unroll
            for (int nf = 0; nf < 2 * NG; nf++) {
                int c = warpN * (COUT / WN) + nf * 8 + (lane & 3) * 2;
                Cs[r * CSTR + c]           = acc[mt][nf][0] + prm[388 + c];
                Cs[r * CSTR + c + 1]       = acc[mt][nf][1] + prm[388 + c + 1];
                Cs[(r + 8) * CSTR + c]     = acc[mt][nf][2] + prm[388 + c];
                Cs[(r + 8) * CSTR + c + 1] = acc[mt][nf][3] + prm[388 + c + 1];
            }
        }
        __syncthreads();
        if (tid < BM) {
            int r = row0 + tid;
            float o0 = prm[384], o1 = prm[385], o2 = prm[386];
            const float *crow = Cs + tid * CSTR;
#pragma unroll 16
            for (int k = 0; k < COUT; k++) {
                float v = crow[k];
                o0 = fmaf(v, prm[3 * k + 0], o0);
                o1 = fmaf(v, prm[3 * k + 1], o1);
                o2 = fmaf(v, prm[3 * k + 2], o2);
            }
            if (r < N) {
                float *o = (float *)Y + ((size_t)b * N + r) * 3;
                o[0] = o0; o[1] = o1; o[2] = o2;
            }
        }
    }
}

// ---------------------------------------------------------------------------
extern "C" void kernel_launch(void *const *d_in, const int *in_sizes, int n_in,
                              void *d_out, int out_size) {
    const float *x   = (const float *)d_in[0];
    const int   *idx = (const int *)d_in[1];
    const float *W0  = (const float *)d_in[2];
    const float *b0  = (const float *)d_in[3];
    const float *W1  = (const float *)d_in[4];
    const float *b1  = (const float *)d_in[5];
    const float *W2  = (const float *)d_in[6];
    const float *b2  = (const float *)d_in[7];
    const float *W3  = (const float *)d_in[8];
    const float *b3  = (const float *)d_in[9];
    const float *Wf  = (const float *)d_in[10];
    const float *bf  = (const float *)d_in[11];
    float *out = (float *)d_out;

    int N = in_sizes[1] / SPI;
    int B = in_sizes[0] / (N * 3);

    __nv_bfloat16 *bufX, *bufY;
    cudaGetSymbolAddress((void **)&bufX, g_bufX);
    cudaGetSymbolAddress((void **)&bufY, g_bufY);
    uint4 *wf1, *wf2, *wf3;
    cudaGetSymbolAddress((void **)&wf1, g_WF1);
    cudaGetSymbolAddress((void **)&wf2, g_WF2);
    cudaGetSymbolAddress((void **)&wf3, g_WF3);

    constexpr int SMN1 = 65536 + 4608 + 32 * 4;
    constexpr int SMN2 = 65536 + 4608 + 64 * 4;
    constexpr int SMF  = 65536 + 4608 + (384 + 4 + 128) * 4;
    cudaFuncSetAttribute(layer_mma<16, 32, false>,
                         cudaFuncAttributeMaxDynamicSharedMemorySize, SMN1);
    cudaFuncSetAttribute(layer_mma<32, 64, false>,
                         cudaFuncAttributeMaxDynamicSharedMemorySize, SMN2);
    cudaFuncSetAttribute(layer_mma<64, 128, true>,
                         cudaFuncAttributeMaxDynamicSharedMemorySize, SMF);

    prep_wfrag<16, 32><<<9, 256>>>(W1, wf1);
    prep_wfrag<32, 64><<<9, 256>>>(W2, wf2);
    prep_wfrag<64, 128><<<9, 256>>>(W3, wf3);

    dim3 g0((N + 255) / 256, B);
    layer0_kernel<<<g0, 256>>>(x, idx, W0, b0, bufX, N);

    dim3 gl((N + BM - 1) / BM, B);
    layer_mma<16, 32, false><<<gl, 256, SMN1>>>(bufX, idx, b1, wf1,
                                                nullptr, nullptr, bufY, N);
    layer_mma<32, 64, false><<<gl, 256, SMN2>>>(bufY, idx, b2, wf2,
                                                nullptr, nullptr, bufX, N);
    layer_mma<64, 128, true><<<gl, 256, SMF>>>(bufX, idx, b3, wf3,
                                               Wf, bf, out, N);
}